// round 1
// baseline (speedup 1.0000x reference)
#include <cuda_runtime.h>
#include <cstdint>

#define NV   100000
#define MPAD 100096          // 782 * 128
#define NG   64
#define HIDN 256

// ---------------- scratch (device globals; no allocation allowed) ----------------
__device__ float d_norm[NV];
__device__ float d_s [(size_t)NV * 256];     // scaled current features (gather source)
__device__ float d_g [(size_t)NV * 256];     // scatter-add accumulator
__device__ float d_z1[(size_t)MPAD * 384];   // layer1 concat [h | h1 | h2]
__device__ float d_x1[(size_t)MPAD * 256];
__device__ float d_z2[(size_t)MPAD * 768];   // layer2 concat
__device__ float d_x2[(size_t)MPAD * 256];
__device__ float d_pooled[NG * HIDN];

// ---------------- utility kernels ----------------
__global__ void k_zero(float4* __restrict__ p, long n4) {
    long i = (long)blockIdx.x * blockDim.x + threadIdx.x;
    if (i < n4) p[i] = make_float4(0.f, 0.f, 0.f, 0.f);
}

__global__ void k_deg(const int* __restrict__ dst, int E) {
    int i = blockIdx.x * blockDim.x + threadIdx.x;
    if (i < E) atomicAdd(&d_norm[dst[i]], 1.0f);
}

__global__ void k_rsqrt() {
    int i = blockIdx.x * blockDim.x + threadIdx.x;
    if (i < NV) d_norm[i] = rsqrtf(fmaxf(d_norm[i], 1.0f));
}

// v = in[i,:] (optionally * norm[i]); write into z (concat slot); optionally s = v * norm[i]
__global__ void k_prep(const float4* __restrict__ in, float4* __restrict__ z,
                       float4* __restrict__ s, int sh, int zs4, int mulNorm) {
    long idx = (long)blockIdx.x * blockDim.x + threadIdx.x;
    long total = (long)NV << sh;
    if (idx >= total) return;
    int i = (int)(idx >> sh);
    int j = (int)(idx & ((1 << sh) - 1));
    float n = d_norm[i];
    float4 v = in[idx];
    if (mulNorm) { v.x *= n; v.y *= n; v.z *= n; v.w *= n; }
    z[(long)i * zs4 + j] = v;
    if (s) {
        float4 sv = make_float4(v.x * n, v.y * n, v.z * n, v.w * n);
        s[idx] = sv;
    }
}

// scatter-add: g[dst[e],:] += s[src[e],:]  (LPE = d/4 lanes per edge, float4 per lane)
template <int LPE>
__global__ __launch_bounds__(256) void k_scatter(const float4* __restrict__ s,
                                                 float* __restrict__ g,
                                                 const int* __restrict__ src,
                                                 const int* __restrict__ dst, int E) {
    const int epb = 256 / LPE;
    int e = blockIdx.x * epb + threadIdx.x / LPE;
    int lane = threadIdx.x % LPE;
    if (e >= E) return;
    int sv = __ldg(&src[e]);
    int dv = __ldg(&dst[e]);
    float4 v = __ldg(&s[(long)sv * LPE + lane]);
    float* out = g + (long)dv * (LPE * 4) + lane * 4;
    asm volatile("red.global.add.v4.f32 [%0], {%1, %2, %3, %4};"
                 :: "l"(out), "f"(v.x), "f"(v.y), "f"(v.z), "f"(v.w) : "memory");
}

// C[M,256] = relu(A[M,K] @ B[K,256] + bias), 128x128 block tile, 8x8 microtile
__global__ __launch_bounds__(256) void k_gemm_relu(const float* __restrict__ A,
                                                   const float* __restrict__ B,
                                                   const float* __restrict__ bias,
                                                   float* __restrict__ C,
                                                   int Kdim, int Ncols) {
    __shared__ float As[8][132];
    __shared__ float Bs[8][128];
    const int tid = threadIdx.x;
    const int tx = tid & 15;     // col group 0..15
    const int ty = tid >> 4;     // row group 0..15
    const long mbase = (long)blockIdx.y * 128;
    const int  nbase = blockIdx.x * 128;

    const int arow = tid >> 1;          // 0..127
    const int acol = (tid & 1) * 4;     // 0 or 4
    const int brow = tid >> 5;          // 0..7
    const int bcol = (tid & 31) * 4;

    const float* Aptr = A + (mbase + arow) * (long)Kdim + acol;
    const float* Bptr = B + (long)brow * Ncols + nbase + bcol;

    float acc[8][8];
#pragma unroll
    for (int i = 0; i < 8; i++)
#pragma unroll
        for (int j = 0; j < 8; j++) acc[i][j] = 0.f;

    for (int k0 = 0; k0 < Kdim; k0 += 8) {
        float4 av = *(const float4*)(Aptr + k0);
        float4 bv = *(const float4*)(Bptr + (long)k0 * Ncols);
        As[acol + 0][arow] = av.x;
        As[acol + 1][arow] = av.y;
        As[acol + 2][arow] = av.z;
        As[acol + 3][arow] = av.w;
        *(float4*)&Bs[brow][bcol] = bv;
        __syncthreads();
#pragma unroll
        for (int kk = 0; kk < 8; kk++) {
            float a[8], b[8];
#pragma unroll
            for (int i = 0; i < 8; i++) a[i] = As[kk][ty * 8 + i];
#pragma unroll
            for (int j = 0; j < 8; j++) b[j] = Bs[kk][tx * 8 + j];
#pragma unroll
            for (int i = 0; i < 8; i++)
#pragma unroll
                for (int j = 0; j < 8; j++)
                    acc[i][j] = fmaf(a[i], b[j], acc[i][j]);
        }
        __syncthreads();
    }
#pragma unroll
    for (int i = 0; i < 8; i++) {
        long row = mbase + ty * 8 + i;
        float* Cp = C + row * Ncols + nbase + tx * 8;
#pragma unroll
        for (int j = 0; j < 8; j++) {
            float v = acc[i][j] + bias[nbase + tx * 8 + j];
            Cp[j] = v > 0.f ? v : 0.f;
        }
    }
}

// segment max over sorted graph_ids; pooled pre-zeroed (relu outputs >= 0)
__global__ void k_segmax(const float* __restrict__ x, const int* __restrict__ gid,
                         int rowsPerBlock) {
    int col = threadIdx.x;               // 256 cols
    int r0 = blockIdx.x * rowsPerBlock;
    if (r0 >= NV) return;
    int r1 = min(r0 + rowsPerBlock, NV);
    int g = __ldg(&gid[r0]);
    float m = 0.f;
    for (int r = r0; r < r1; r++) {
        int g2 = __ldg(&gid[r]);
        if (g2 != g) {
            atomicMax((int*)&d_pooled[g * HIDN + col], __float_as_int(m));
            m = 0.f;
            g = g2;
        }
        m = fmaxf(m, x[(long)r * HIDN + col]);
    }
    atomicMax((int*)&d_pooled[g * HIDN + col], __float_as_int(m));
}

__global__ void k_head(const float* __restrict__ Wc, const float* __restrict__ bc,
                       float* __restrict__ out) {
    int t = blockIdx.x * blockDim.x + threadIdx.x;
    if (t >= NG * 10) return;
    int g = t / 10, c = t % 10;
    float s = bc[c];
#pragma unroll 8
    for (int h = 0; h < HIDN; h++) s = fmaf(d_pooled[g * HIDN + h], Wc[h * 10 + c], s);
    out[t] = s;
}

// ---------------- launch ----------------
extern "C" void kernel_launch(void* const* d_in, const int* in_sizes, int n_in,
                              void* d_out, int out_size) {
    const float* h   = (const float*)d_in[0];
    const int*   src = (const int*)d_in[1];
    const int*   dst = (const int*)d_in[2];
    const int*   gid = (const int*)d_in[3];
    const float* W1  = (const float*)d_in[4];
    const float* b1  = (const float*)d_in[5];
    const float* W2  = (const float*)d_in[6];
    const float* b2  = (const float*)d_in[7];
    const float* Wc  = (const float*)d_in[8];
    const float* bc  = (const float*)d_in[9];
    float* out = (float*)d_out;
    const int E = in_sizes[1];

    float *nm_, *s_, *g_, *z1_, *x1_, *z2_, *x2_;
    cudaGetSymbolAddress((void**)&nm_, d_norm);
    cudaGetSymbolAddress((void**)&s_,  d_s);
    cudaGetSymbolAddress((void**)&g_,  d_g);
    cudaGetSymbolAddress((void**)&z1_, d_z1);
    cudaGetSymbolAddress((void**)&x1_, d_x1);
    cudaGetSymbolAddress((void**)&z2_, d_z2);
    cudaGetSymbolAddress((void**)&x2_, d_x2);
    float* pl_;
    cudaGetSymbolAddress((void**)&pl_, d_pooled);

    auto zero = [](float* p, long n4) {
        k_zero<<<(unsigned)((n4 + 255) / 256), 256>>>((float4*)p, n4);
    };

    // degree -> norm
    zero(nm_, NV / 4);
    k_deg<<<(E + 255) / 256, 256>>>(dst, E);
    k_rsqrt<<<(NV + 255) / 256, 256>>>();

    const long n4_128 = (long)NV * 32;   // NV * 128 / 4
    const long n4_256 = (long)NV * 64;

    // ---- layer 1 (d = 128, sh = 5, z stride 96 f4) ----
    k_prep<<<(unsigned)((n4_128 + 255) / 256), 256>>>((const float4*)h, (float4*)z1_,
                                                       (float4*)s_, 5, 96, 0);
    zero(g_, n4_128);
    k_scatter<32><<<(E + 7) / 8, 256>>>((const float4*)s_, g_, src, dst, E);
    k_prep<<<(unsigned)((n4_128 + 255) / 256), 256>>>((const float4*)g_, (float4*)z1_ + 32,
                                                       (float4*)s_, 5, 96, 1);
    zero(g_, n4_128);
    k_scatter<32><<<(E + 7) / 8, 256>>>((const float4*)s_, g_, src, dst, E);
    k_prep<<<(unsigned)((n4_128 + 255) / 256), 256>>>((const float4*)g_, (float4*)z1_ + 64,
                                                       nullptr, 5, 96, 1);
    k_gemm_relu<<<dim3(2, MPAD / 128), 256>>>(z1_, W1, b1, x1_, 384, 256);

    // ---- layer 2 (d = 256, sh = 6, z stride 192 f4) ----
    k_prep<<<(unsigned)((n4_256 + 255) / 256), 256>>>((const float4*)x1_, (float4*)z2_,
                                                       (float4*)s_, 6, 192, 0);
    zero(g_, n4_256);
    k_scatter<64><<<(E + 3) / 4, 256>>>((const float4*)s_, g_, src, dst, E);
    k_prep<<<(unsigned)((n4_256 + 255) / 256), 256>>>((const float4*)g_, (float4*)z2_ + 64,
                                                       (float4*)s_, 6, 192, 1);
    zero(g_, n4_256);
    k_scatter<64><<<(E + 3) / 4, 256>>>((const float4*)s_, g_, src, dst, E);
    k_prep<<<(unsigned)((n4_256 + 255) / 256), 256>>>((const float4*)g_, (float4*)z2_ + 128,
                                                       nullptr, 6, 192, 1);
    k_gemm_relu<<<dim3(2, MPAD / 128), 256>>>(z2_, W2, b2, x2_, 768, 256);

    // ---- pooling + head ----
    zero(pl_, NG * HIDN / 4);
    k_segmax<<<(NV + 511) / 512, 256>>>(x2_, gid, 512);
    k_head<<<3, 256>>>(Wc, bc, out);
}

// round 2
// speedup vs baseline: 1.2638x; 1.2638x over previous
#include <cuda_runtime.h>
#include <cstdint>

#define NV   100000
#define MPAD 100096          // 782 * 128
#define NG   64
#define HIDN 256

// ---------------- scratch (device globals; no allocation allowed) ----------------
__device__ float d_norm[NV];
__device__ float d_s [(size_t)NV * 256];     // scaled current features (gather source)
__device__ float d_g [(size_t)NV * 256];     // scatter-add accumulator
__device__ float d_z1[(size_t)MPAD * 384];   // layer1 concat [h | h1 | h2]
__device__ float d_x1[(size_t)MPAD * 256];
__device__ float d_z2[(size_t)MPAD * 768];   // layer2 concat
__device__ float d_x2[(size_t)MPAD * 256];
__device__ float d_pooled[NG * HIDN];

// ---------------- utility kernels ----------------
__global__ void k_zero(float4* __restrict__ p, long n4) {
    long i = (long)blockIdx.x * blockDim.x + threadIdx.x;
    if (i < n4) p[i] = make_float4(0.f, 0.f, 0.f, 0.f);
}

__global__ void k_deg(const int* __restrict__ dst, int E) {
    int i = blockIdx.x * blockDim.x + threadIdx.x;
    if (i < E) atomicAdd(&d_norm[dst[i]], 1.0f);
}

__global__ void k_rsqrt() {
    int i = blockIdx.x * blockDim.x + threadIdx.x;
    if (i < NV) d_norm[i] = rsqrtf(fmaxf(d_norm[i], 1.0f));
}

// v = in[i,:] (optionally * norm[i]); write into z (concat slot); optionally s = v * norm[i]
__global__ void k_prep(const float4* __restrict__ in, float4* __restrict__ z,
                       float4* __restrict__ s, int sh, int zs4, int mulNorm) {
    long idx = (long)blockIdx.x * blockDim.x + threadIdx.x;
    long total = (long)NV << sh;
    if (idx >= total) return;
    int i = (int)(idx >> sh);
    int j = (int)(idx & ((1 << sh) - 1));
    float n = d_norm[i];
    float4 v = in[idx];
    if (mulNorm) { v.x *= n; v.y *= n; v.z *= n; v.w *= n; }
    z[(long)i * zs4 + j] = v;
    if (s) {
        float4 sv = make_float4(v.x * n, v.y * n, v.z * n, v.w * n);
        s[idx] = sv;
    }
}

// scatter-add: g[dst[e],:] += s[src[e],:]  (LPE = d/4 lanes per edge, float4 per lane)
template <int LPE>
__global__ __launch_bounds__(256) void k_scatter(const float4* __restrict__ s,
                                                 float* __restrict__ g,
                                                 const int* __restrict__ src,
                                                 const int* __restrict__ dst, int E) {
    const int epb = 256 / LPE;
    int e = blockIdx.x * epb + threadIdx.x / LPE;
    int lane = threadIdx.x % LPE;
    if (e >= E) return;
    int sv = __ldg(&src[e]);
    int dv = __ldg(&dst[e]);
    float4 v = __ldg(&s[(long)sv * LPE + lane]);
    float* out = g + (long)dv * (LPE * 4) + lane * 4;
    asm volatile("red.global.add.v4.f32 [%0], {%1, %2, %3, %4};"
                 :: "l"(out), "f"(v.x), "f"(v.y), "f"(v.z), "f"(v.w) : "memory");
}

// ---------------- TF32 tensor-core GEMM ----------------
// C[M,256] = relu(A[M,K] @ B[K,256] + bias)
// 128x128x32 block tile, 8 warps (2M x 4N), warp tile 64x32, mma m16n8k8 tf32.
#define BM 128
#define BN 128
#define BK 32
#define AS_STRIDE 36    // (4*gid + qid) covers all 32 banks -> conflict-free frag loads
#define BS_STRIDE 136   // (8*qid + gid) covers all 32 banks -> conflict-free frag loads
#define AS_SZ (BM * AS_STRIDE)            // 4608 floats
#define BS_SZ (BK * BS_STRIDE)            // 4352 floats
#define STAGE_SZ (AS_SZ + BS_SZ)          // 8960 floats
#define GEMM_SMEM_BYTES (2 * STAGE_SZ * 4)

extern __shared__ float smem_gemm[];

__device__ __forceinline__ void cp_async16(float* s, const float* g) {
    uint32_t sa = (uint32_t)__cvta_generic_to_shared(s);
    asm volatile("cp.async.cg.shared.global [%0], [%1], 16;\n" :: "r"(sa), "l"(g));
}
__device__ __forceinline__ void cp_commit() { asm volatile("cp.async.commit_group;\n"); }
template <int N>
__device__ __forceinline__ void cp_wait() { asm volatile("cp.async.wait_group %0;\n" :: "n"(N)); }

__device__ __forceinline__ uint32_t f2tf32(float f) {
    uint32_t r;
    asm("cvt.rna.tf32.f32 %0, %1;" : "=r"(r) : "f"(f));
    return r;
}

__device__ __forceinline__ void mma_tf32(float* c, const uint32_t* a, const uint32_t* b) {
    asm volatile(
        "mma.sync.aligned.m16n8k8.row.col.f32.tf32.tf32.f32 "
        "{%0,%1,%2,%3}, {%4,%5,%6,%7}, {%8,%9}, {%0,%1,%2,%3};"
        : "+f"(c[0]), "+f"(c[1]), "+f"(c[2]), "+f"(c[3])
        : "r"(a[0]), "r"(a[1]), "r"(a[2]), "r"(a[3]), "r"(b[0]), "r"(b[1]));
}

__global__ __launch_bounds__(256) void k_gemm_tf32(const float* __restrict__ A,
                                                   const float* __restrict__ B,
                                                   const float* __restrict__ bias,
                                                   float* __restrict__ C,
                                                   int Kdim, int Ncols) {
    const int tid  = threadIdx.x;
    const int lane = tid & 31, warp = tid >> 5;
    const int gid  = lane >> 2, qid = lane & 3;
    const int wm   = (warp & 1) * 64;
    const int wn   = (warp >> 1) * 32;
    const long mbase = (long)blockIdx.y * BM;
    const int  nbase = blockIdx.x * BN;

    float acc[4][4][4];
#pragma unroll
    for (int mi = 0; mi < 4; mi++)
#pragma unroll
        for (int ni = 0; ni < 4; ni++)
#pragma unroll
            for (int r = 0; r < 4; r++) acc[mi][ni][r] = 0.f;

    const int ntiles = Kdim / BK;

    auto load_stage = [&](int t, int buf) {
        float* As = smem_gemm + buf * STAGE_SZ;
        float* Bs = As + AS_SZ;
        const float* Ag = A + mbase * Kdim + t * BK;
        const float* Bg = B + (long)t * BK * Ncols + nbase;
#pragma unroll
        for (int i = 0; i < 4; i++) {
            int ch = tid + 256 * i;
            int m = ch & 127, kc = ch >> 7;        // kc in 0..7
            cp_async16(As + m * AS_STRIDE + kc * 4, Ag + (long)m * Kdim + kc * 4);
        }
#pragma unroll
        for (int i = 0; i < 4; i++) {
            int ch = tid + 256 * i;
            int kr = ch >> 5, nc = ch & 31;        // kr 0..31, nc 0..31
            cp_async16(Bs + kr * BS_STRIDE + nc * 4, Bg + (long)kr * Ncols + nc * 4);
        }
        cp_commit();
    };

    load_stage(0, 0);
    for (int t = 0; t < ntiles; t++) {
        int buf = t & 1;
        if (t + 1 < ntiles) { load_stage(t + 1, buf ^ 1); cp_wait<1>(); }
        else                { cp_wait<0>(); }
        __syncthreads();
        const float* As = smem_gemm + buf * STAGE_SZ;
        const float* Bs = As + AS_SZ;
#pragma unroll
        for (int kk = 0; kk < BK; kk += 8) {
            uint32_t af[4][4], bf[4][2];
#pragma unroll
            for (int mi = 0; mi < 4; mi++) {
                int r = wm + mi * 16 + gid;
                af[mi][0] = f2tf32(As[r * AS_STRIDE + kk + qid]);
                af[mi][1] = f2tf32(As[(r + 8) * AS_STRIDE + kk + qid]);
                af[mi][2] = f2tf32(As[r * AS_STRIDE + kk + qid + 4]);
                af[mi][3] = f2tf32(As[(r + 8) * AS_STRIDE + kk + qid + 4]);
            }
#pragma unroll
            for (int ni = 0; ni < 4; ni++) {
                int c = wn + ni * 8 + gid;
                bf[ni][0] = f2tf32(Bs[(kk + qid) * BS_STRIDE + c]);
                bf[ni][1] = f2tf32(Bs[(kk + qid + 4) * BS_STRIDE + c]);
            }
#pragma unroll
            for (int mi = 0; mi < 4; mi++)
#pragma unroll
                for (int ni = 0; ni < 4; ni++)
                    mma_tf32(acc[mi][ni], af[mi], bf[ni]);
        }
        __syncthreads();
    }

    // epilogue: bias + relu
#pragma unroll
    for (int mi = 0; mi < 4; mi++) {
        long row = mbase + wm + mi * 16 + gid;
#pragma unroll
        for (int ni = 0; ni < 4; ni++) {
            int col = nbase + wn + ni * 8 + 2 * qid;
            float b0 = bias[col], b1 = bias[col + 1];
            float2 v0, v1;
            v0.x = fmaxf(acc[mi][ni][0] + b0, 0.f);
            v0.y = fmaxf(acc[mi][ni][1] + b1, 0.f);
            v1.x = fmaxf(acc[mi][ni][2] + b0, 0.f);
            v1.y = fmaxf(acc[mi][ni][3] + b1, 0.f);
            *(float2*)&C[row * Ncols + col]       = v0;
            *(float2*)&C[(row + 8) * Ncols + col] = v1;
        }
    }
}

// segment max over sorted graph_ids; pooled pre-zeroed (relu outputs >= 0)
__global__ void k_segmax(const float* __restrict__ x, const int* __restrict__ gid,
                         int rowsPerBlock) {
    int col = threadIdx.x;               // 256 cols
    int r0 = blockIdx.x * rowsPerBlock;
    if (r0 >= NV) return;
    int r1 = min(r0 + rowsPerBlock, NV);
    int g = __ldg(&gid[r0]);
    float m = 0.f;
    for (int r = r0; r < r1; r++) {
        int g2 = __ldg(&gid[r]);
        if (g2 != g) {
            atomicMax((int*)&d_pooled[g * HIDN + col], __float_as_int(m));
            m = 0.f;
            g = g2;
        }
        m = fmaxf(m, x[(long)r * HIDN + col]);
    }
    atomicMax((int*)&d_pooled[g * HIDN + col], __float_as_int(m));
}

__global__ void k_head(const float* __restrict__ Wc, const float* __restrict__ bc,
                       float* __restrict__ out) {
    int t = blockIdx.x * blockDim.x + threadIdx.x;
    if (t >= NG * 10) return;
    int g = t / 10, c = t % 10;
    float s = bc[c];
#pragma unroll 8
    for (int h = 0; h < HIDN; h++) s = fmaf(d_pooled[g * HIDN + h], Wc[h * 10 + c], s);
    out[t] = s;
}

// ---------------- launch ----------------
extern "C" void kernel_launch(void* const* d_in, const int* in_sizes, int n_in,
                              void* d_out, int out_size) {
    const float* h   = (const float*)d_in[0];
    const int*   src = (const int*)d_in[1];
    const int*   dst = (const int*)d_in[2];
    const int*   gid = (const int*)d_in[3];
    const float* W1  = (const float*)d_in[4];
    const float* b1  = (const float*)d_in[5];
    const float* W2  = (const float*)d_in[6];
    const float* b2  = (const float*)d_in[7];
    const float* Wc  = (const float*)d_in[8];
    const float* bc  = (const float*)d_in[9];
    float* out = (float*)d_out;
    const int E = in_sizes[1];

    float *nm_, *s_, *g_, *z1_, *x1_, *z2_, *x2_, *pl_;
    cudaGetSymbolAddress((void**)&nm_, d_norm);
    cudaGetSymbolAddress((void**)&s_,  d_s);
    cudaGetSymbolAddress((void**)&g_,  d_g);
    cudaGetSymbolAddress((void**)&z1_, d_z1);
    cudaGetSymbolAddress((void**)&x1_, d_x1);
    cudaGetSymbolAddress((void**)&z2_, d_z2);
    cudaGetSymbolAddress((void**)&x2_, d_x2);
    cudaGetSymbolAddress((void**)&pl_, d_pooled);

    cudaFuncSetAttribute(k_gemm_tf32, cudaFuncAttributeMaxDynamicSharedMemorySize,
                         GEMM_SMEM_BYTES);

    auto zero = [](float* p, long n4) {
        k_zero<<<(unsigned)((n4 + 255) / 256), 256>>>((float4*)p, n4);
    };

    // degree -> norm
    zero(nm_, NV / 4);
    k_deg<<<(E + 255) / 256, 256>>>(dst, E);
    k_rsqrt<<<(NV + 255) / 256, 256>>>();

    const long n4_128 = (long)NV * 32;   // NV * 128 / 4
    const long n4_256 = (long)NV * 64;

    // ---- layer 1 (d = 128, sh = 5, z stride 96 f4) ----
    k_prep<<<(unsigned)((n4_128 + 255) / 256), 256>>>((const float4*)h, (float4*)z1_,
                                                       (float4*)s_, 5, 96, 0);
    zero(g_, n4_128);
    k_scatter<32><<<(E + 7) / 8, 256>>>((const float4*)s_, g_, src, dst, E);
    k_prep<<<(unsigned)((n4_128 + 255) / 256), 256>>>((const float4*)g_, (float4*)z1_ + 32,
                                                       (float4*)s_, 5, 96, 1);
    zero(g_, n4_128);
    k_scatter<32><<<(E + 7) / 8, 256>>>((const float4*)s_, g_, src, dst, E);
    k_prep<<<(unsigned)((n4_128 + 255) / 256), 256>>>((const float4*)g_, (float4*)z1_ + 64,
                                                       nullptr, 5, 96, 1);
    k_gemm_tf32<<<dim3(2, MPAD / 128), 256, GEMM_SMEM_BYTES>>>(z1_, W1, b1, x1_, 384, 256);

    // ---- layer 2 (d = 256, sh = 6, z stride 192 f4) ----
    k_prep<<<(unsigned)((n4_256 + 255) / 256), 256>>>((const float4*)x1_, (float4*)z2_,
                                                       (float4*)s_, 6, 192, 0);
    zero(g_, n4_256);
    k_scatter<64><<<(E + 3) / 4, 256>>>((const float4*)s_, g_, src, dst, E);
    k_prep<<<(unsigned)((n4_256 + 255) / 256), 256>>>((const float4*)g_, (float4*)z2_ + 64,
                                                       (float4*)s_, 6, 192, 1);
    zero(g_, n4_256);
    k_scatter<64><<<(E + 3) / 4, 256>>>((const float4*)s_, g_, src, dst, E);
    k_prep<<<(unsigned)((n4_256 + 255) / 256), 256>>>((const float4*)g_, (float4*)z2_ + 128,
                                                       nullptr, 6, 192, 1);
    k_gemm_tf32<<<dim3(2, MPAD / 128), 256, GEMM_SMEM_BYTES>>>(z2_, W2, b2, x2_, 768, 256);

    // ---- pooling + head ----
    zero(pl_, NG * HIDN / 4);
    k_segmax<<<(NV + 511) / 512, 256>>>(x2_, gid, 512);
    k_head<<<3, 256>>>(Wc, bc, out);
}

// round 3
// speedup vs baseline: 3.0245x; 2.3932x over previous
#include <cuda_runtime.h>
#include <cstdint>

#define NV   100000
#define MPAD 100096          // 782 * 128
#define NG   64
#define HIDN 256
#define EMAX 3211264

// ---------------- scratch (device globals; no allocation allowed) ----------------
__device__ float d_norm[NV];
__device__ int   d_cnt[NV];
__device__ int   d_rowptr[NV + 1];
__device__ int   d_cursor[NV];
__device__ int   d_blktot[128];
__device__ int   d_blkoff[128];
__device__ int   d_esrc[EMAX];
__device__ float d_s [(size_t)NV * 256];     // scaled features ping
__device__ float d_g [(size_t)NV * 256];     // scaled features pong
__device__ float d_z1[(size_t)MPAD * 384];   // layer1 concat (tf32-rounded)
__device__ float d_z2[(size_t)MPAD * 768];   // layer2 concat (tf32-rounded)
__device__ float d_x2[(size_t)MPAD * 256];
__device__ float d_w1t[384 * 256];
__device__ float d_w2t[768 * 256];
__device__ float d_pooled[NG * HIDN];

__device__ __forceinline__ float tf32r(float f) {
    uint32_t r;
    asm("cvt.rna.tf32.f32 %0, %1;" : "=r"(r) : "f"(f));
    return __uint_as_float(r);
}

// ---------------- utility kernels ----------------
__global__ void k_zero(float4* __restrict__ p, long n4) {
    long i = (long)blockIdx.x * blockDim.x + threadIdx.x;
    if (i < n4) p[i] = make_float4(0.f, 0.f, 0.f, 0.f);
}

__global__ void k_degi(const int* __restrict__ dst, int E) {
    int i = blockIdx.x * blockDim.x + threadIdx.x;
    if (i < E) atomicAdd(&d_cnt[dst[i]], 1);
}

__global__ void k_norm_from_cnt() {
    int i = blockIdx.x * blockDim.x + threadIdx.x;
    if (i < NV) d_norm[i] = rsqrtf(fmaxf((float)d_cnt[i], 1.0f));
}

// ---------------- prefix scan (1024 elems / block) ----------------
__global__ __launch_bounds__(256) void k_scan_local() {
    __shared__ int sh[256];
    int b = blockIdx.x, t = threadIdx.x;
    int base = b * 1024 + t * 4;
    int c[4];
#pragma unroll
    for (int i = 0; i < 4; i++) c[i] = (base + i < NV) ? d_cnt[base + i] : 0;
    int sum = c[0] + c[1] + c[2] + c[3];
    sh[t] = sum;
    __syncthreads();
    for (int off = 1; off < 256; off <<= 1) {
        int x = (t >= off) ? sh[t - off] : 0;
        __syncthreads();
        sh[t] += x;
        __syncthreads();
    }
    int run = sh[t] - sum;   // exclusive offset within block
#pragma unroll
    for (int i = 0; i < 4; i++) {
        if (base + i < NV) d_rowptr[base + i] = run;
        run += c[i];
    }
    if (t == 255) d_blktot[b] = sh[255];
}

__global__ void k_scan_blk(int nb) {
    if (threadIdx.x == 0) {
        int run = 0;
        for (int b = 0; b < nb; b++) { d_blkoff[b] = run; run += d_blktot[b]; }
    }
}

__global__ void k_addoff(int E) {
    int i = blockIdx.x * blockDim.x + threadIdx.x;
    if (i < NV) {
        int v = d_rowptr[i] + d_blkoff[i >> 10];
        d_rowptr[i] = v;
        d_cursor[i] = v;
    }
    if (i == 0) d_rowptr[NV] = E;
}

__global__ void k_csrbuild(const int* __restrict__ src, const int* __restrict__ dst, int E) {
    int e = blockIdx.x * blockDim.x + threadIdx.x;
    if (e < E) {
        int p = atomicAdd(&d_cursor[dst[e]], 1);
        d_esrc[p] = src[e];
    }
}

// round weights to tf32 once
__global__ void k_round(float* __restrict__ o, const float* __restrict__ in, int n) {
    int i = blockIdx.x * blockDim.x + threadIdx.x;
    if (i < n) o[i] = tf32r(in[i]);
}

// prep0: z1 slot0 = tf32(h); s = h * norm
__global__ void k_prep0(const float4* __restrict__ in, float4* __restrict__ z,
                        float4* __restrict__ s) {
    long idx = (long)blockIdx.x * blockDim.x + threadIdx.x;
    if (idx >= (long)NV * 32) return;
    int i = (int)(idx >> 5), j = (int)(idx & 31);
    float n = d_norm[i];
    float4 v = in[idx];
    float4 zr = make_float4(tf32r(v.x), tf32r(v.y), tf32r(v.z), tf32r(v.w));
    z[(long)i * 96 + j] = zr;
    s[idx] = make_float4(v.x * n, v.y * n, v.z * n, v.w * n);
}

// ---------------- CSR aggregation (one LPE-lane group per node) ----------------
// cur = (sum_{e in CSR[v]} s[esrc[e]]) * norm[v];  z[v] = tf32(cur);  s_next[v] = cur*norm[v]
template <int LPE, bool WRITE_S>
__global__ __launch_bounds__(256) void k_agg(const float4* __restrict__ s,
                                             float4* __restrict__ z, int zs4,
                                             float4* __restrict__ s_next) {
    const int gpb = 256 / LPE;
    int v = blockIdx.x * gpb + threadIdx.x / LPE;
    int lane = threadIdx.x % LPE;
    if (v >= NV) return;
    int beg = __ldg(&d_rowptr[v]);
    int end = __ldg(&d_rowptr[v + 1]);
    float4 a0 = make_float4(0.f, 0.f, 0.f, 0.f);
    float4 a1 = make_float4(0.f, 0.f, 0.f, 0.f);
    int e = beg;
    for (; e + 1 < end; e += 2) {
        int s0 = __ldg(&d_esrc[e]);
        int s1 = __ldg(&d_esrc[e + 1]);
        float4 v0 = __ldg(&s[(long)s0 * LPE + lane]);
        float4 v1 = __ldg(&s[(long)s1 * LPE + lane]);
        a0.x += v0.x; a0.y += v0.y; a0.z += v0.z; a0.w += v0.w;
        a1.x += v1.x; a1.y += v1.y; a1.z += v1.z; a1.w += v1.w;
    }
    if (e < end) {
        float4 v0 = __ldg(&s[(long)__ldg(&d_esrc[e]) * LPE + lane]);
        a0.x += v0.x; a0.y += v0.y; a0.z += v0.z; a0.w += v0.w;
    }
    float n = __ldg(&d_norm[v]);
    float4 cur;
    cur.x = (a0.x + a1.x) * n;
    cur.y = (a0.y + a1.y) * n;
    cur.z = (a0.z + a1.z) * n;
    cur.w = (a0.w + a1.w) * n;
    z[(long)v * zs4 + lane] = make_float4(tf32r(cur.x), tf32r(cur.y), tf32r(cur.z), tf32r(cur.w));
    if (WRITE_S)
        s_next[(long)v * LPE + lane] = make_float4(cur.x * n, cur.y * n, cur.z * n, cur.w * n);
}

// ---------------- TF32 tensor-core GEMM ----------------
// inputs pre-rounded to tf32; no cvt in the mainloop.
#define BM 128
#define BN 128
#define BK 32
#define AS_STRIDE 36
#define BS_STRIDE 136
#define AS_SZ (BM * AS_STRIDE)
#define BS_SZ (BK * BS_STRIDE)
#define STAGE_SZ (AS_SZ + BS_SZ)
#define GEMM_SMEM_BYTES (2 * STAGE_SZ * 4)

extern __shared__ float smem_gemm[];

__device__ __forceinline__ void cp_async16(float* s, const float* g) {
    uint32_t sa = (uint32_t)__cvta_generic_to_shared(s);
    asm volatile("cp.async.cg.shared.global [%0], [%1], 16;\n" :: "r"(sa), "l"(g));
}
__device__ __forceinline__ void cp_commit() { asm volatile("cp.async.commit_group;\n"); }
template <int N>
__device__ __forceinline__ void cp_wait() { asm volatile("cp.async.wait_group %0;\n" :: "n"(N)); }

__device__ __forceinline__ void mma_tf32(float* c, const uint32_t* a, const uint32_t* b) {
    asm volatile(
        "mma.sync.aligned.m16n8k8.row.col.f32.tf32.tf32.f32 "
        "{%0,%1,%2,%3}, {%4,%5,%6,%7}, {%8,%9}, {%0,%1,%2,%3};"
        : "+f"(c[0]), "+f"(c[1]), "+f"(c[2]), "+f"(c[3])
        : "r"(a[0]), "r"(a[1]), "r"(a[2]), "r"(a[3]), "r"(b[0]), "r"(b[1]));
}

// EPI=0: C[row*Ncols+col] = relu(acc+bias)
// EPI=1: zOut[row*768+col] = tf32(relu(acc+bias)); sOut[row*256+col] = relu(..)*norm (row<NV)
template <int EPI>
__global__ __launch_bounds__(256) void k_gemm_tf32(const float* __restrict__ A,
                                                   const float* __restrict__ B,
                                                   const float* __restrict__ bias,
                                                   float* __restrict__ C,
                                                   int Kdim, int Ncols,
                                                   float* __restrict__ zOut,
                                                   float* __restrict__ sOut) {
    const int tid  = threadIdx.x;
    const int lane = tid & 31, warp = tid >> 5;
    const int gid  = lane >> 2, qid = lane & 3;
    const int wm   = (warp & 1) * 64;
    const int wn   = (warp >> 1) * 32;
    const long mbase = (long)blockIdx.y * BM;
    const int  nbase = blockIdx.x * BN;

    float acc[4][4][4];
#pragma unroll
    for (int mi = 0; mi < 4; mi++)
#pragma unroll
        for (int ni = 0; ni < 4; ni++)
#pragma unroll
            for (int r = 0; r < 4; r++) acc[mi][ni][r] = 0.f;

    const int ntiles = Kdim / BK;

    auto load_stage = [&](int t, int buf) {
        float* As = smem_gemm + buf * STAGE_SZ;
        float* Bs = As + AS_SZ;
        const float* Ag = A + mbase * Kdim + t * BK;
        const float* Bg = B + (long)t * BK * Ncols + nbase;
#pragma unroll
        for (int i = 0; i < 4; i++) {
            int ch = tid + 256 * i;
            int m = ch & 127, kc = ch >> 7;
            cp_async16(As + m * AS_STRIDE + kc * 4, Ag + (long)m * Kdim + kc * 4);
        }
#pragma unroll
        for (int i = 0; i < 4; i++) {
            int ch = tid + 256 * i;
            int kr = ch >> 5, nc = ch & 31;
            cp_async16(Bs + kr * BS_STRIDE + nc * 4, Bg + (long)kr * Ncols + nc * 4);
        }
        cp_commit();
    };

    load_stage(0, 0);
    for (int t = 0; t < ntiles; t++) {
        int buf = t & 1;
        if (t + 1 < ntiles) { load_stage(t + 1, buf ^ 1); cp_wait<1>(); }
        else                { cp_wait<0>(); }
        __syncthreads();
        const float* As = smem_gemm + buf * STAGE_SZ;
        const float* Bs = As + AS_SZ;
#pragma unroll
        for (int kk = 0; kk < BK; kk += 8) {
            uint32_t af[4][4], bf[4][2];
#pragma unroll
            for (int mi = 0; mi < 4; mi++) {
                int r = wm + mi * 16 + gid;
                af[mi][0] = __float_as_uint(As[r * AS_STRIDE + kk + qid]);
                af[mi][1] = __float_as_uint(As[(r + 8) * AS_STRIDE + kk + qid]);
                af[mi][2] = __float_as_uint(As[r * AS_STRIDE + kk + qid + 4]);
                af[mi][3] = __float_as_uint(As[(r + 8) * AS_STRIDE + kk + qid + 4]);
            }
#pragma unroll
            for (int ni = 0; ni < 4; ni++) {
                int c = wn + ni * 8 + gid;
                bf[ni][0] = __float_as_uint(Bs[(kk + qid) * BS_STRIDE + c]);
                bf[ni][1] = __float_as_uint(Bs[(kk + qid + 4) * BS_STRIDE + c]);
            }
#pragma unroll
            for (int mi = 0; mi < 4; mi++)
#pragma unroll
                for (int ni = 0; ni < 4; ni++)
                    mma_tf32(acc[mi][ni], af[mi], bf[ni]);
        }
        __syncthreads();
    }

#pragma unroll
    for (int mi = 0; mi < 4; mi++) {
        long r0 = mbase + wm + mi * 16 + gid;
        long r1 = r0 + 8;
        float n0 = 0.f, n1 = 0.f;
        if (EPI == 1) {
            n0 = (r0 < NV) ? d_norm[r0] : 0.f;
            n1 = (r1 < NV) ? d_norm[r1] : 0.f;
        }
#pragma unroll
        for (int ni = 0; ni < 4; ni++) {
            int col = nbase + wn + ni * 8 + 2 * qid;
            float b0 = bias[col], b1v = bias[col + 1];
            float v00 = fmaxf(acc[mi][ni][0] + b0, 0.f);
            float v01 = fmaxf(acc[mi][ni][1] + b1v, 0.f);
            float v10 = fmaxf(acc[mi][ni][2] + b0, 0.f);
            float v11 = fmaxf(acc[mi][ni][3] + b1v, 0.f);
            if (EPI == 0) {
                *(float2*)&C[r0 * Ncols + col] = make_float2(v00, v01);
                *(float2*)&C[r1 * Ncols + col] = make_float2(v10, v11);
            } else {
                *(float2*)&zOut[r0 * 768 + col] = make_float2(tf32r(v00), tf32r(v01));
                *(float2*)&zOut[r1 * 768 + col] = make_float2(tf32r(v10), tf32r(v11));
                if (r0 < NV) *(float2*)&sOut[r0 * 256 + col] = make_float2(v00 * n0, v01 * n0);
                if (r1 < NV) *(float2*)&sOut[r1 * 256 + col] = make_float2(v10 * n1, v11 * n1);
            }
        }
    }
}

// segment max over sorted graph_ids; pooled pre-zeroed (relu outputs >= 0)
__global__ void k_segmax(const float* __restrict__ x, const int* __restrict__ gid,
                         int rowsPerBlock) {
    int col = threadIdx.x;
    int r0 = blockIdx.x * rowsPerBlock;
    if (r0 >= NV) return;
    int r1 = min(r0 + rowsPerBlock, NV);
    int g = __ldg(&gid[r0]);
    float m = 0.f;
    for (int r = r0; r < r1; r++) {
        int g2 = __ldg(&gid[r]);
        if (g2 != g) {
            atomicMax((int*)&d_pooled[g * HIDN + col], __float_as_int(m));
            m = 0.f;
            g = g2;
        }
        m = fmaxf(m, x[(long)r * HIDN + col]);
    }
    atomicMax((int*)&d_pooled[g * HIDN + col], __float_as_int(m));
}

__global__ void k_head(const float* __restrict__ Wc, const float* __restrict__ bc,
                       float* __restrict__ out) {
    int t = blockIdx.x * blockDim.x + threadIdx.x;
    if (t >= NG * 10) return;
    int g = t / 10, c = t % 10;
    float s = bc[c];
#pragma unroll 8
    for (int h = 0; h < HIDN; h++) s = fmaf(d_pooled[g * HIDN + h], Wc[h * 10 + c], s);
    out[t] = s;
}

// ---------------- launch ----------------
extern "C" void kernel_launch(void* const* d_in, const int* in_sizes, int n_in,
                              void* d_out, int out_size) {
    const float* h   = (const float*)d_in[0];
    const int*   src = (const int*)d_in[1];
    const int*   dst = (const int*)d_in[2];
    const int*   gid = (const int*)d_in[3];
    const float* W1  = (const float*)d_in[4];
    const float* b1  = (const float*)d_in[5];
    const float* W2  = (const float*)d_in[6];
    const float* b2  = (const float*)d_in[7];
    const float* Wc  = (const float*)d_in[8];
    const float* bc  = (const float*)d_in[9];
    float* out = (float*)d_out;
    const int E = in_sizes[1];

    float *s_, *g_, *z1_, *z2_, *x2_, *pl_, *w1t_, *w2t_;
    int *cnt_;
    cudaGetSymbolAddress((void**)&s_,   d_s);
    cudaGetSymbolAddress((void**)&g_,   d_g);
    cudaGetSymbolAddress((void**)&z1_,  d_z1);
    cudaGetSymbolAddress((void**)&z2_,  d_z2);
    cudaGetSymbolAddress((void**)&x2_,  d_x2);
    cudaGetSymbolAddress((void**)&pl_,  d_pooled);
    cudaGetSymbolAddress((void**)&w1t_, d_w1t);
    cudaGetSymbolAddress((void**)&w2t_, d_w2t);
    cudaGetSymbolAddress((void**)&cnt_, d_cnt);

    cudaFuncSetAttribute(k_gemm_tf32<0>, cudaFuncAttributeMaxDynamicSharedMemorySize,
                         GEMM_SMEM_BYTES);
    cudaFuncSetAttribute(k_gemm_tf32<1>, cudaFuncAttributeMaxDynamicSharedMemorySize,
                         GEMM_SMEM_BYTES);

    // ---- degree, norm, CSR ----
    k_zero<<<(NV / 4 + 255) / 256, 256>>>((float4*)cnt_, NV / 4);
    k_degi<<<(E + 255) / 256, 256>>>(dst, E);
    k_norm_from_cnt<<<(NV + 255) / 256, 256>>>();
    const int NB = (NV + 1023) / 1024;
    k_scan_local<<<NB, 256>>>();
    k_scan_blk<<<1, 32>>>(NB);
    k_addoff<<<(NV + 255) / 256, 256>>>(E);
    k_csrbuild<<<(E + 255) / 256, 256>>>(src, dst, E);

    // ---- weights -> tf32 ----
    k_round<<<(384 * 256 + 255) / 256, 256>>>(w1t_, W1, 384 * 256);
    k_round<<<(768 * 256 + 255) / 256, 256>>>(w2t_, W2, 768 * 256);

    // ---- layer 1 (d=128, z stride 96 f4) ----
    k_prep0<<<(unsigned)(((long)NV * 32 + 255) / 256), 256>>>((const float4*)h,
                                                              (float4*)z1_, (float4*)s_);
    k_agg<32, true ><<<(NV + 7) / 8, 256>>>((const float4*)s_, (float4*)z1_ + 32, 96,
                                            (float4*)g_);
    k_agg<32, false><<<(NV + 7) / 8, 256>>>((const float4*)g_, (float4*)z1_ + 64, 96,
                                            nullptr);
    k_gemm_tf32<1><<<dim3(2, MPAD / 128), 256, GEMM_SMEM_BYTES>>>(z1_, w1t_, b1, nullptr,
                                                                  384, 256, z2_, s_);

    // ---- layer 2 (d=256, z stride 192 f4) ----
    k_agg<64, true ><<<(NV + 3) / 4, 256>>>((const float4*)s_, (float4*)z2_ + 64, 192,
                                            (float4*)g_);
    k_agg<64, false><<<(NV + 3) / 4, 256>>>((const float4*)g_, (float4*)z2_ + 128, 192,
                                            nullptr);
    k_gemm_tf32<0><<<dim3(2, MPAD / 128), 256, GEMM_SMEM_BYTES>>>(z2_, w2t_, b2, x2_,
                                                                  768, 256, nullptr, nullptr);

    // ---- pooling + head ----
    k_zero<<<(NG * HIDN / 4 + 255) / 256, 256>>>((float4*)pl_, NG * HIDN / 4);
    k_segmax<<<(NV + 511) / 512, 256>>>(x2_, gid, 512);
    k_head<<<3, 256>>>(Wc, bc, out);
}

// round 4
// speedup vs baseline: 3.9201x; 1.2961x over previous
#include <cuda_runtime.h>
#include <cuda_fp16.h>
#include <cstdint>

#define NV   100000
#define MPAD 100096          // 782 * 128
#define NG   64
#define HIDN 256
#define EMAX 3211264

// ---------------- scratch (device globals; no allocation allowed) ----------------
__device__ float  d_norm[NV];
__device__ int    d_cnt[NV];
__device__ int    d_rowptr[NV + 1];
__device__ int    d_cursor[NV];
__device__ int    d_blktot[128];
__device__ int    d_blkoff[128];
__device__ int    d_esrc[EMAX];
__device__ __half d_s [(size_t)NV * 256];    // scaled features ping (fp16)
__device__ __half d_g [(size_t)NV * 256];    // scaled features pong (fp16)
__device__ float  d_z1[(size_t)MPAD * 384];  // layer1 concat (tf32-rounded fp32)
__device__ float  d_z2[(size_t)MPAD * 768];  // layer2 concat
__device__ float  d_x2[(size_t)MPAD * 256];
__device__ float  d_w1t[384 * 256];
__device__ float  d_w2t[768 * 256];
__device__ float  d_pooled[NG * HIDN];

__device__ __forceinline__ float tf32r(float f) {
    uint32_t r;
    asm("cvt.rna.tf32.f32 %0, %1;" : "=r"(r) : "f"(f));
    return __uint_as_float(r);
}

// ---------------- utility kernels ----------------
__global__ void k_zero(float4* __restrict__ p, long n4) {
    long i = (long)blockIdx.x * blockDim.x + threadIdx.x;
    if (i < n4) p[i] = make_float4(0.f, 0.f, 0.f, 0.f);
}

__global__ void k_degi(const int* __restrict__ dst, int E) {
    int i = blockIdx.x * blockDim.x + threadIdx.x;
    if (i < E) atomicAdd(&d_cnt[dst[i]], 1);
}

__global__ void k_norm_from_cnt() {
    int i = blockIdx.x * blockDim.x + threadIdx.x;
    if (i < NV) d_norm[i] = rsqrtf(fmaxf((float)d_cnt[i], 1.0f));
}

// ---------------- prefix scan (1024 elems / block) ----------------
__global__ __launch_bounds__(256) void k_scan_local() {
    __shared__ int sh[256];
    int b = blockIdx.x, t = threadIdx.x;
    int base = b * 1024 + t * 4;
    int c[4];
#pragma unroll
    for (int i = 0; i < 4; i++) c[i] = (base + i < NV) ? d_cnt[base + i] : 0;
    int sum = c[0] + c[1] + c[2] + c[3];
    sh[t] = sum;
    __syncthreads();
    for (int off = 1; off < 256; off <<= 1) {
        int x = (t >= off) ? sh[t - off] : 0;
        __syncthreads();
        sh[t] += x;
        __syncthreads();
    }
    int run = sh[t] - sum;
#pragma unroll
    for (int i = 0; i < 4; i++) {
        if (base + i < NV) d_rowptr[base + i] = run;
        run += c[i];
    }
    if (t == 255) d_blktot[b] = sh[255];
}

__global__ void k_scan_blk(int nb) {
    if (threadIdx.x == 0) {
        int run = 0;
        for (int b = 0; b < nb; b++) { d_blkoff[b] = run; run += d_blktot[b]; }
    }
}

__global__ void k_addoff(int E) {
    int i = blockIdx.x * blockDim.x + threadIdx.x;
    if (i < NV) {
        int v = d_rowptr[i] + d_blkoff[i >> 10];
        d_rowptr[i] = v;
        d_cursor[i] = v;
    }
    if (i == 0) d_rowptr[NV] = E;
}

__global__ void k_csrbuild(const int* __restrict__ src, const int* __restrict__ dst, int E) {
    int e = blockIdx.x * blockDim.x + threadIdx.x;
    if (e < E) {
        int p = atomicAdd(&d_cursor[dst[e]], 1);
        d_esrc[p] = src[e];
    }
}

__global__ void k_round(float* __restrict__ o, const float* __restrict__ in, int n) {
    int i = blockIdx.x * blockDim.x + threadIdx.x;
    if (i < n) o[i] = tf32r(in[i]);
}

// prep0: z1 slot0 = tf32(h); s(fp16) = h * norm
__global__ void k_prep0(const float4* __restrict__ in, float4* __restrict__ z,
                        uint2* __restrict__ s) {
    long idx = (long)blockIdx.x * blockDim.x + threadIdx.x;
    if (idx >= (long)NV * 32) return;
    int i = (int)(idx >> 5), j = (int)(idx & 31);
    float n = d_norm[i];
    float4 v = in[idx];
    z[(long)i * 96 + j] = make_float4(tf32r(v.x), tf32r(v.y), tf32r(v.z), tf32r(v.w));
    __half2 p0 = __floats2half2_rn(v.x * n, v.y * n);
    __half2 p1 = __floats2half2_rn(v.z * n, v.w * n);
    uint2 u;
    u.x = *(uint32_t*)&p0;
    u.y = *(uint32_t*)&p1;
    s[idx] = u;
}

// ---------------- CSR aggregation ----------------
// One group of D/8 lanes per node; each lane owns 8 halves (one uint4).
// cur = (sum_{e in CSR[v]} s[esrc[e]]) * norm[v]; z[v]=tf32(cur); s_next[v]=fp16(cur*norm[v])
template <int D, bool WRITE_S>
__global__ __launch_bounds__(256) void k_agg(const __half* __restrict__ s,
                                             float* __restrict__ z, int zrow,
                                             __half* __restrict__ s_next) {
    const int LPE = D / 8;
    const int gpb = 256 / LPE;
    int v = blockIdx.x * gpb + threadIdx.x / LPE;
    int lane = threadIdx.x % LPE;
    if (v >= NV) return;
    int beg = __ldg(&d_rowptr[v]);
    int end = __ldg(&d_rowptr[v + 1]);
    float a0[8], a1[8];
#pragma unroll
    for (int i = 0; i < 8; i++) { a0[i] = 0.f; a1[i] = 0.f; }

    auto accum = [&](float* a, int node) {
        const uint4 u = __ldg((const uint4*)(s + (size_t)node * D) + lane);
        __half2 h0 = *(const __half2*)&u.x;
        __half2 h1 = *(const __half2*)&u.y;
        __half2 h2 = *(const __half2*)&u.z;
        __half2 h3 = *(const __half2*)&u.w;
        float2 f0 = __half22float2(h0);
        float2 f1 = __half22float2(h1);
        float2 f2 = __half22float2(h2);
        float2 f3 = __half22float2(h3);
        a[0] += f0.x; a[1] += f0.y; a[2] += f1.x; a[3] += f1.y;
        a[4] += f2.x; a[5] += f2.y; a[6] += f3.x; a[7] += f3.y;
    };

    int e = beg;
    for (; e + 1 < end; e += 2) {
        int s0 = __ldg(&d_esrc[e]);
        int s1 = __ldg(&d_esrc[e + 1]);
        accum(a0, s0);
        accum(a1, s1);
    }
    if (e < end) accum(a0, __ldg(&d_esrc[e]));

    float n = __ldg(&d_norm[v]);
    float cur[8];
#pragma unroll
    for (int i = 0; i < 8; i++) cur[i] = (a0[i] + a1[i]) * n;

    float* zp = z + (long)v * zrow + lane * 8;
    ((float4*)zp)[0] = make_float4(tf32r(cur[0]), tf32r(cur[1]), tf32r(cur[2]), tf32r(cur[3]));
    ((float4*)zp)[1] = make_float4(tf32r(cur[4]), tf32r(cur[5]), tf32r(cur[6]), tf32r(cur[7]));

    if (WRITE_S) {
        __half2 o0 = __floats2half2_rn(cur[0] * n, cur[1] * n);
        __half2 o1 = __floats2half2_rn(cur[2] * n, cur[3] * n);
        __half2 o2 = __floats2half2_rn(cur[4] * n, cur[5] * n);
        __half2 o3 = __floats2half2_rn(cur[6] * n, cur[7] * n);
        uint4 u;
        u.x = *(uint32_t*)&o0; u.y = *(uint32_t*)&o1;
        u.z = *(uint32_t*)&o2; u.w = *(uint32_t*)&o3;
        ((uint4*)(s_next + (size_t)v * D))[lane] = u;
    }
}

// ---------------- TF32 tensor-core GEMM (3-stage cp.async pipeline) ----------------
#define BM 128
#define BN 128
#define BK 32
#define AS_STRIDE 36
#define BS_STRIDE 136
#define AS_SZ (BM * AS_STRIDE)
#define BS_SZ (BK * BS_STRIDE)
#define STAGE_SZ (AS_SZ + BS_SZ)
#define NSTAGE 3
#define GEMM_SMEM_BYTES (NSTAGE * STAGE_SZ * 4)

extern __shared__ float smem_gemm[];

__device__ __forceinline__ void cp_async16(float* s, const float* g) {
    uint32_t sa = (uint32_t)__cvta_generic_to_shared(s);
    asm volatile("cp.async.cg.shared.global [%0], [%1], 16;\n" :: "r"(sa), "l"(g));
}
__device__ __forceinline__ void cp_commit() { asm volatile("cp.async.commit_group;\n"); }
template <int N>
__device__ __forceinline__ void cp_wait() { asm volatile("cp.async.wait_group %0;\n" :: "n"(N)); }

__device__ __forceinline__ void mma_tf32(float* c, const uint32_t* a, const uint32_t* b) {
    asm volatile(
        "mma.sync.aligned.m16n8k8.row.col.f32.tf32.tf32.f32 "
        "{%0,%1,%2,%3}, {%4,%5,%6,%7}, {%8,%9}, {%0,%1,%2,%3};"
        : "+f"(c[0]), "+f"(c[1]), "+f"(c[2]), "+f"(c[3])
        : "r"(a[0]), "r"(a[1]), "r"(a[2]), "r"(a[3]), "r"(b[0]), "r"(b[1]));
}

// EPI=0: C = relu(acc+bias)
// EPI=1: zOut[row*768+col] = tf32(relu); sOut(fp16)[row*256+col] = relu*norm (row<NV)
template <int EPI>
__global__ __launch_bounds__(256) void k_gemm_tf32(const float* __restrict__ A,
                                                   const float* __restrict__ B,
                                                   const float* __restrict__ bias,
                                                   float* __restrict__ C,
                                                   int Kdim, int Ncols,
                                                   float* __restrict__ zOut,
                                                   __half* __restrict__ sOut) {
    const int tid  = threadIdx.x;
    const int lane = tid & 31, warp = tid >> 5;
    const int gid  = lane >> 2, qid = lane & 3;
    const int wm   = (warp & 1) * 64;
    const int wn   = (warp >> 1) * 32;
    const long mbase = (long)blockIdx.y * BM;
    const int  nbase = blockIdx.x * BN;

    float acc[4][4][4];
#pragma unroll
    for (int mi = 0; mi < 4; mi++)
#pragma unroll
        for (int ni = 0; ni < 4; ni++)
#pragma unroll
            for (int r = 0; r < 4; r++) acc[mi][ni][r] = 0.f;

    const int ntiles = Kdim / BK;

    auto load_stage = [&](int t, int buf) {
        float* As = smem_gemm + buf * STAGE_SZ;
        float* Bs = As + AS_SZ;
        const float* Ag = A + mbase * Kdim + t * BK;
        const float* Bg = B + (long)t * BK * Ncols + nbase;
#pragma unroll
        for (int i = 0; i < 4; i++) {
            int ch = tid + 256 * i;
            int m = ch & 127, kc = ch >> 7;
            cp_async16(As + m * AS_STRIDE + kc * 4, Ag + (long)m * Kdim + kc * 4);
        }
#pragma unroll
        for (int i = 0; i < 4; i++) {
            int ch = tid + 256 * i;
            int kr = ch >> 5, nc = ch & 31;
            cp_async16(Bs + kr * BS_STRIDE + nc * 4, Bg + (long)kr * Ncols + nc * 4);
        }
        cp_commit();
    };

    load_stage(0, 0);
    load_stage(1, 1);
    for (int t = 0; t < ntiles; t++) {
        if (t + 2 < ntiles) { load_stage(t + 2, (t + 2) % NSTAGE); cp_wait<2>(); }
        else if (t + 1 < ntiles) cp_wait<1>();
        else cp_wait<0>();
        __syncthreads();
        const float* As = smem_gemm + (t % NSTAGE) * STAGE_SZ;
        const float* Bs = As + AS_SZ;
#pragma unroll
        for (int kk = 0; kk < BK; kk += 8) {
            uint32_t af[4][4], bf[4][2];
#pragma unroll
            for (int mi = 0; mi < 4; mi++) {
                int r = wm + mi * 16 + gid;
                af[mi][0] = __float_as_uint(As[r * AS_STRIDE + kk + qid]);
                af[mi][1] = __float_as_uint(As[(r + 8) * AS_STRIDE + kk + qid]);
                af[mi][2] = __float_as_uint(As[r * AS_STRIDE + kk + qid + 4]);
                af[mi][3] = __float_as_uint(As[(r + 8) * AS_STRIDE + kk + qid + 4]);
            }
#pragma unroll
            for (int ni = 0; ni < 4; ni++) {
                int c = wn + ni * 8 + gid;
                bf[ni][0] = __float_as_uint(Bs[(kk + qid) * BS_STRIDE + c]);
                bf[ni][1] = __float_as_uint(Bs[(kk + qid + 4) * BS_STRIDE + c]);
            }
#pragma unroll
            for (int mi = 0; mi < 4; mi++)
#pragma unroll
                for (int ni = 0; ni < 4; ni++)
                    mma_tf32(acc[mi][ni], af[mi], bf[ni]);
        }
        __syncthreads();
    }

#pragma unroll
    for (int mi = 0; mi < 4; mi++) {
        long r0 = mbase + wm + mi * 16 + gid;
        long r1 = r0 + 8;
        float n0 = 0.f, n1 = 0.f;
        if (EPI == 1) {
            n0 = (r0 < NV) ? d_norm[r0] : 0.f;
            n1 = (r1 < NV) ? d_norm[r1] : 0.f;
        }
#pragma unroll
        for (int ni = 0; ni < 4; ni++) {
            int col = nbase + wn + ni * 8 + 2 * qid;
            float b0 = bias[col], b1v = bias[col + 1];
            float v00 = fmaxf(acc[mi][ni][0] + b0, 0.f);
            float v01 = fmaxf(acc[mi][ni][1] + b1v, 0.f);
            float v10 = fmaxf(acc[mi][ni][2] + b0, 0.f);
            float v11 = fmaxf(acc[mi][ni][3] + b1v, 0.f);
            if (EPI == 0) {
                *(float2*)&C[r0 * Ncols + col] = make_float2(v00, v01);
                *(float2*)&C[r1 * Ncols + col] = make_float2(v10, v11);
            } else {
                *(float2*)&zOut[r0 * 768 + col] = make_float2(tf32r(v00), tf32r(v01));
                *(float2*)&zOut[r1 * 768 + col] = make_float2(tf32r(v10), tf32r(v11));
                if (r0 < NV) {
                    __half2 hv = __floats2half2_rn(v00 * n0, v01 * n0);
                    *(__half2*)&sOut[r0 * 256 + col] = hv;
                }
                if (r1 < NV) {
                    __half2 hv = __floats2half2_rn(v10 * n1, v11 * n1);
                    *(__half2*)&sOut[r1 * 256 + col] = hv;
                }
            }
        }
    }
}

// segment max over sorted graph_ids; pooled pre-zeroed (relu outputs >= 0)
__global__ void k_segmax(const float* __restrict__ x, const int* __restrict__ gid,
                         int rowsPerBlock) {
    int col = threadIdx.x;
    int r0 = blockIdx.x * rowsPerBlock;
    if (r0 >= NV) return;
    int r1 = min(r0 + rowsPerBlock, NV);
    int g = __ldg(&gid[r0]);
    float m = 0.f;
    for (int r = r0; r < r1; r++) {
        int g2 = __ldg(&gid[r]);
        if (g2 != g) {
            atomicMax((int*)&d_pooled[g * HIDN + col], __float_as_int(m));
            m = 0.f;
            g = g2;
        }
        m = fmaxf(m, x[(long)r * HIDN + col]);
    }
    atomicMax((int*)&d_pooled[g * HIDN + col], __float_as_int(m));
}

__global__ void k_head(const float* __restrict__ Wc, const float* __restrict__ bc,
                       float* __restrict__ out) {
    int t = blockIdx.x * blockDim.x + threadIdx.x;
    if (t >= NG * 10) return;
    int g = t / 10, c = t % 10;
    float s = bc[c];
#pragma unroll 8
    for (int h = 0; h < HIDN; h++) s = fmaf(d_pooled[g * HIDN + h], Wc[h * 10 + c], s);
    out[t] = s;
}

// ---------------- launch ----------------
extern "C" void kernel_launch(void* const* d_in, const int* in_sizes, int n_in,
                              void* d_out, int out_size) {
    const float* h   = (const float*)d_in[0];
    const int*   src = (const int*)d_in[1];
    const int*   dst = (const int*)d_in[2];
    const int*   gid = (const int*)d_in[3];
    const float* W1  = (const float*)d_in[4];
    const float* b1  = (const float*)d_in[5];
    const float* W2  = (const float*)d_in[6];
    const float* b2  = (const float*)d_in[7];
    const float* Wc  = (const float*)d_in[8];
    const float* bc  = (const float*)d_in[9];
    float* out = (float*)d_out;
    const int E = in_sizes[1];

    float *z1_, *z2_, *x2_, *pl_, *w1t_, *w2t_;
    __half *s_, *g_;
    int *cnt_;
    cudaGetSymbolAddress((void**)&s_,   d_s);
    cudaGetSymbolAddress((void**)&g_,   d_g);
    cudaGetSymbolAddress((void**)&z1_,  d_z1);
    cudaGetSymbolAddress((void**)&z2_,  d_z2);
    cudaGetSymbolAddress((void**)&x2_,  d_x2);
    cudaGetSymbolAddress((void**)&pl_,  d_pooled);
    cudaGetSymbolAddress((void**)&w1t_, d_w1t);
    cudaGetSymbolAddress((void**)&w2t_, d_w2t);
    cudaGetSymbolAddress((void**)&cnt_, d_cnt);

    cudaFuncSetAttribute(k_gemm_tf32<0>, cudaFuncAttributeMaxDynamicSharedMemorySize,
                         GEMM_SMEM_BYTES);
    cudaFuncSetAttribute(k_gemm_tf32<1>, cudaFuncAttributeMaxDynamicSharedMemorySize,
                         GEMM_SMEM_BYTES);

    // ---- degree, norm, CSR ----
    k_zero<<<(NV / 4 + 255) / 256, 256>>>((float4*)cnt_, NV / 4);
    k_degi<<<(E + 255) / 256, 256>>>(dst, E);
    k_norm_from_cnt<<<(NV + 255) / 256, 256>>>();
    const int NB = (NV + 1023) / 1024;
    k_scan_local<<<NB, 256>>>();
    k_scan_blk<<<1, 32>>>(NB);
    k_addoff<<<(NV + 255) / 256, 256>>>(E);
    k_csrbuild<<<(E + 255) / 256, 256>>>(src, dst, E);

    // ---- weights -> tf32 ----
    k_round<<<(384 * 256 + 255) / 256, 256>>>(w1t_, W1, 384 * 256);
    k_round<<<(768 * 256 + 255) / 256, 256>>>(w2t_, W2, 768 * 256);

    // ---- layer 1 (d=128) ----
    k_prep0<<<(unsigned)(((long)NV * 32 + 255) / 256), 256>>>((const float4*)h,
                                                              (float4*)z1_, (uint2*)s_);
    k_agg<128, true ><<<(NV + 15) / 16, 256>>>(s_, z1_ + 128, 384, g_);
    k_agg<128, false><<<(NV + 15) / 16, 256>>>(g_, z1_ + 256, 384, nullptr);
    k_gemm_tf32<1><<<dim3(2, MPAD / 128), 256, GEMM_SMEM_BYTES>>>(z1_, w1t_, b1, nullptr,
                                                                  384, 256, z2_, s_);

    // ---- layer 2 (d=256) ----
    k_agg<256, true ><<<(NV + 7) / 8, 256>>>(s_, z2_ + 256, 768, g_);
    k_agg<256, false><<<(NV + 7) / 8, 256>>>(g_, z2_ + 512, 768, nullptr);
    k_gemm_tf32<0><<<dim3(2, MPAD / 128), 256, GEMM_SMEM_BYTES>>>(z2_, w2t_, b2, x2_,
                                                                  768, 256, nullptr, nullptr);

    // ---- pooling + head ----
    k_zero<<<(NG * HIDN / 4 + 255) / 256, 256>>>((float4*)pl_, NG * HIDN / 4);
    k_segmax<<<(NV + 511) / 512, 256>>>(x2_, gid, 512);
    k_head<<<3, 256>>>(Wc, bc, out);
}

// round 5
// speedup vs baseline: 5.7556x; 1.4682x over previous
#include <cuda_runtime.h>
#include <cuda_fp16.h>
#include <cstdint>

#define NV   100000
#define MPAD 100096          // 782 * 128
#define NG   64
#define HIDN 256
#define EMAX 3211264

// ---------------- scratch (device globals; no allocation allowed) ----------------
__device__ float  d_norm[NV];
__device__ int    d_cnt[NV];
__device__ int    d_rowptr[NV + 1];
__device__ int    d_cursor[NV];
__device__ int    d_blktot[128];
__device__ int    d_blkoff[128];
__device__ int    d_esrc[EMAX];
__device__ __half d_h16 [(size_t)MPAD * 128];   // GEMM1 slot0 (pad rows stay 0)
__device__ __half d_hop1[(size_t)MPAD * 128];   // GEMM1 slot1
__device__ __half d_hop2[(size_t)MPAD * 128];   // GEMM1 slot2
__device__ __half d_x1h [(size_t)MPAD * 256];   // GEMM2 slot0
__device__ __half d_g1  [(size_t)MPAD * 256];   // GEMM2 slot1
__device__ __half d_g2  [(size_t)MPAD * 256];   // GEMM2 slot2
__device__ __half d_sA  [(size_t)NV * 256];     // gather source ping
__device__ __half d_sB  [(size_t)NV * 256];     // gather source pong
__device__ float  d_x2  [(size_t)MPAD * 256];
__device__ __half d_w1h[384 * 256];
__device__ __half d_w2h[768 * 256];
__device__ float  d_pooled[NG * HIDN];

// ---------------- utility kernels ----------------
__global__ void k_zero(float4* __restrict__ p, long n4) {
    long i = (long)blockIdx.x * blockDim.x + threadIdx.x;
    if (i < n4) p[i] = make_float4(0.f, 0.f, 0.f, 0.f);
}

__global__ void k_degi(const int* __restrict__ dst, int E) {
    int i = blockIdx.x * blockDim.x + threadIdx.x;
    if (i < E) atomicAdd(&d_cnt[dst[i]], 1);
}

__global__ void k_norm_from_cnt() {
    int i = blockIdx.x * blockDim.x + threadIdx.x;
    if (i < NV) d_norm[i] = rsqrtf(fmaxf((float)d_cnt[i], 1.0f));
}

// ---------------- prefix scan (1024 elems / block) ----------------
__global__ __launch_bounds__(256) void k_scan_local() {
    __shared__ int sh[256];
    int b = blockIdx.x, t = threadIdx.x;
    int base = b * 1024 + t * 4;
    int c[4];
#pragma unroll
    for (int i = 0; i < 4; i++) c[i] = (base + i < NV) ? d_cnt[base + i] : 0;
    int sum = c[0] + c[1] + c[2] + c[3];
    sh[t] = sum;
    __syncthreads();
    for (int off = 1; off < 256; off <<= 1) {
        int x = (t >= off) ? sh[t - off] : 0;
        __syncthreads();
        sh[t] += x;
        __syncthreads();
    }
    int run = sh[t] - sum;
#pragma unroll
    for (int i = 0; i < 4; i++) {
        if (base + i < NV) d_rowptr[base + i] = run;
        run += c[i];
    }
    if (t == 255) d_blktot[b] = sh[255];
}

__global__ void k_scan_blk(int nb) {
    if (threadIdx.x == 0) {
        int run = 0;
        for (int b = 0; b < nb; b++) { d_blkoff[b] = run; run += d_blktot[b]; }
    }
}

__global__ void k_addoff(int E) {
    int i = blockIdx.x * blockDim.x + threadIdx.x;
    if (i < NV) {
        int v = d_rowptr[i] + d_blkoff[i >> 10];
        d_rowptr[i] = v;
        d_cursor[i] = v;
    }
    if (i == 0) d_rowptr[NV] = E;
}

__global__ void k_csrbuild(const int* __restrict__ src, const int* __restrict__ dst, int E) {
    int e = blockIdx.x * blockDim.x + threadIdx.x;
    if (e < E) {
        int p = atomicAdd(&d_cursor[dst[e]], 1);
        d_esrc[p] = src[e];
    }
}

// fp32 -> fp16 weight conversion
__global__ void k_roundh(__half* __restrict__ o, const float* __restrict__ in, int n2) {
    int i = blockIdx.x * blockDim.x + threadIdx.x;
    if (i < n2) {
        float2 v = ((const float2*)in)[i];
        ((__half2*)o)[i] = __floats2half2_rn(v.x, v.y);
    }
}

__device__ __forceinline__ uint4 pack8h(const float* f) {
    __half2 h0 = __floats2half2_rn(f[0], f[1]);
    __half2 h1 = __floats2half2_rn(f[2], f[3]);
    __half2 h2 = __floats2half2_rn(f[4], f[5]);
    __half2 h3 = __floats2half2_rn(f[6], f[7]);
    uint4 u;
    u.x = *(uint32_t*)&h0; u.y = *(uint32_t*)&h1;
    u.z = *(uint32_t*)&h2; u.w = *(uint32_t*)&h3;
    return u;
}

// prep0: h16 = fp16(h); sA = fp16(h * norm).  idx over NV*16 (8 floats each)
__global__ void k_prep0(const float4* __restrict__ in, uint4* __restrict__ h16,
                        uint4* __restrict__ s) {
    long idx = (long)blockIdx.x * blockDim.x + threadIdx.x;
    if (idx >= (long)NV * 16) return;
    int i = (int)(idx >> 4);
    float n = d_norm[i];
    float4 v0 = in[idx * 2], v1 = in[idx * 2 + 1];
    float f[8]  = {v0.x, v0.y, v0.z, v0.w, v1.x, v1.y, v1.z, v1.w};
    float fs[8];
#pragma unroll
    for (int k = 0; k < 8; k++) fs[k] = f[k] * n;
    h16[idx] = pack8h(f);
    s[idx]   = pack8h(fs);
}

// ---------------- CSR aggregation ----------------
// One group of D/8 lanes per node; each lane owns 8 halves (one uint4).
// cur = (sum s[esrc[e]]) * norm[v];  hop[v]=fp16(cur);  s_next[v]=fp16(cur*norm[v])
template <int D, bool WRITE_S>
__global__ __launch_bounds__(256) void k_agg(const __half* __restrict__ s,
                                             __half* __restrict__ hop,
                                             __half* __restrict__ s_next) {
    const int LPE = D / 8;
    const int gpb = 256 / LPE;
    int v = blockIdx.x * gpb + threadIdx.x / LPE;
    int lane = threadIdx.x % LPE;
    if (v >= NV) return;
    int beg = __ldg(&d_rowptr[v]);
    int end = __ldg(&d_rowptr[v + 1]);
    float a0[8], a1[8];
#pragma unroll
    for (int i = 0; i < 8; i++) { a0[i] = 0.f; a1[i] = 0.f; }

    auto accum = [&](float* a, int node) {
        const uint4 u = __ldg((const uint4*)(s + (size_t)node * D) + lane);
        float2 f0 = __half22float2(*(const __half2*)&u.x);
        float2 f1 = __half22float2(*(const __half2*)&u.y);
        float2 f2 = __half22float2(*(const __half2*)&u.z);
        float2 f3 = __half22float2(*(const __half2*)&u.w);
        a[0] += f0.x; a[1] += f0.y; a[2] += f1.x; a[3] += f1.y;
        a[4] += f2.x; a[5] += f2.y; a[6] += f3.x; a[7] += f3.y;
    };

    int e = beg;
    for (; e + 1 < end; e += 2) {
        int s0 = __ldg(&d_esrc[e]);
        int s1 = __ldg(&d_esrc[e + 1]);
        accum(a0, s0);
        accum(a1, s1);
    }
    if (e < end) accum(a0, __ldg(&d_esrc[e]));

    float n = __ldg(&d_norm[v]);
    float cur[8], curn[8];
#pragma unroll
    for (int i = 0; i < 8; i++) { cur[i] = (a0[i] + a1[i]) * n; curn[i] = cur[i] * n; }

    ((uint4*)(hop + (size_t)v * D))[lane] = pack8h(cur);
    if (WRITE_S)
        ((uint4*)(s_next + (size_t)v * D))[lane] = pack8h(curn);
}

// ---------------- fp16 tensor-core GEMM (ldmatrix + m16n8k16, 3-stage) ----------------
// A gathered from 3 slot buffers of width SW=2^SWS halves; B = weights [K][256] fp16.
#define BM 128
#define BN 128
#define BKH 64                   // k-halves per tile (128 bytes)
#define A_BYTES (BM * 128)       // 16384
#define B_BYTES (BKH * 256)      // 16384
#define STAGE_BYTES (A_BYTES + B_BYTES)
#define NSTAGE 3
#define GEMM_SMEM_BYTES (NSTAGE * STAGE_BYTES)

extern __shared__ char smem_gemm[];

__device__ __forceinline__ void cp16(uint32_t s, const void* g) {
    asm volatile("cp.async.cg.shared.global [%0], [%1], 16;\n" :: "r"(s), "l"(g));
}
__device__ __forceinline__ void cp_commit() { asm volatile("cp.async.commit_group;\n"); }
template <int N>
__device__ __forceinline__ void cp_wait() { asm volatile("cp.async.wait_group %0;\n" :: "n"(N)); }

__device__ __forceinline__ void ldsm4(uint32_t* r, uint32_t a) {
    asm volatile("ldmatrix.sync.aligned.m8n8.x4.shared.b16 {%0,%1,%2,%3}, [%4];"
                 : "=r"(r[0]), "=r"(r[1]), "=r"(r[2]), "=r"(r[3]) : "r"(a));
}
__device__ __forceinline__ void ldsm2t(uint32_t* r, uint32_t a) {
    asm volatile("ldmatrix.sync.aligned.m8n8.x2.trans.shared.b16 {%0,%1}, [%2];"
                 : "=r"(r[0]), "=r"(r[1]) : "r"(a));
}

__device__ __forceinline__ void mma_f16(float* c, const uint32_t* a, const uint32_t* b) {
    asm volatile(
        "mma.sync.aligned.m16n8k16.row.col.f32.f16.f16.f32 "
        "{%0,%1,%2,%3}, {%4,%5,%6,%7}, {%8,%9}, {%0,%1,%2,%3};"
        : "+f"(c[0]), "+f"(c[1]), "+f"(c[2]), "+f"(c[3])
        : "r"(a[0]), "r"(a[1]), "r"(a[2]), "r"(a[3]), "r"(b[0]), "r"(b[1]));
}

// EPI=0: C(fp32)[row*256+col] = relu(acc+bias)
// EPI=1: xOut(fp16)[row*256+col] = relu; sOut(fp16) = relu*norm (rows < NV)
template <int EPI, int SWS>
__global__ __launch_bounds__(256) void k_gemm_f16(const __half* __restrict__ S0,
                                                  const __half* __restrict__ S1,
                                                  const __half* __restrict__ S2,
                                                  const __half* __restrict__ Bh,
                                                  const float* __restrict__ bias,
                                                  float* __restrict__ C, int Kdim,
                                                  __half* __restrict__ xOut,
                                                  __half* __restrict__ sOut) {
    const int SW = 1 << SWS;
    const int tid  = threadIdx.x;
    const int lane = tid & 31, warp = tid >> 5;
    const int gid  = lane >> 2, qid = lane & 3;
    const int wm   = (warp & 1) * 64;
    const int wn   = (warp >> 1) * 32;
    const long mbase = (long)blockIdx.y * BM;
    const int  nbase = blockIdx.x * BN;

    float acc[4][4][4];
#pragma unroll
    for (int mi = 0; mi < 4; mi++)
#pragma unroll
        for (int ni = 0; ni < 4; ni++)
#pragma unroll
            for (int r = 0; r < 4; r++) acc[mi][ni][r] = 0.f;

    const uint32_t smemB = (uint32_t)__cvta_generic_to_shared(smem_gemm);
    const int ntiles = Kdim / BKH;

    auto load_stage = [&](int t, int buf) {
        uint32_t sb = smemB + buf * STAGE_BYTES;
#pragma unroll
        for (int i = 0; i < 4; i++) {
            int ch = tid + 256 * i;
            int r = ch >> 3, kc = ch & 7;
            uint32_t dstA = sb + r * 128 + ((kc * 16) ^ ((r & 7) * 16));
            int kh = t * BKH + kc * 8;
            int sl = kh >> SWS;
            int off = kh & (SW - 1);
            const __half* base = (sl == 0) ? S0 : ((sl == 1) ? S1 : S2);
            cp16(dstA, base + (size_t)(mbase + r) * SW + off);
        }
#pragma unroll
        for (int i = 0; i < 4; i++) {
            int ch = tid + 256 * i;
            int r = ch >> 4, nc = ch & 15;
            uint32_t dstB = sb + A_BYTES + r * 256 + ((nc * 16) ^ ((r & 7) * 16));
            cp16(dstB, Bh + (size_t)(t * BKH + r) * 256 + nbase + nc * 8);
        }
        cp_commit();
    };

    // ldmatrix per-thread invariants
    const int Lr = lane & 7, sub = lane >> 3;
    const int rowLocal = Lr + (sub & 1) * 8;        // A matrix row within 16
    const int ksub16 = (sub >> 1) * 16;             // A k-byte offset of sub-matrix
    const uint32_t xorA = Lr * 16;
    const int bl = lane & 15;                        // B k-row within 16
    const uint32_t xorB = (lane & 7) * 16;

    load_stage(0, 0);
    load_stage(1, 1);
    for (int t = 0; t < ntiles; t++) {
        if (t + 2 < ntiles) { load_stage(t + 2, (t + 2) % NSTAGE); cp_wait<2>(); }
        else if (t + 1 < ntiles) cp_wait<1>();
        else cp_wait<0>();
        __syncthreads();
        uint32_t As = smemB + (t % NSTAGE) * STAGE_BYTES;
        uint32_t Bs = As + A_BYTES;
        uint32_t aRow[4];
#pragma unroll
        for (int mi = 0; mi < 4; mi++)
            aRow[mi] = As + (wm + mi * 16 + rowLocal) * 128;
        uint32_t bBase = Bs + bl * 256;
        uint32_t bOff[4];
#pragma unroll
        for (int ni = 0; ni < 4; ni++)
            bOff[ni] = (uint32_t)((wn + ni * 8) * 2) ^ xorB;
#pragma unroll
        for (int ks = 0; ks < 4; ks++) {
            uint32_t a[4][4], b[4][2];
#pragma unroll
            for (int mi = 0; mi < 4; mi++)
                ldsm4(a[mi], aRow[mi] + (uint32_t)((ks * 32 + ksub16) ^ xorA));
#pragma unroll
            for (int ni = 0; ni < 4; ni++)
                ldsm2t(b[ni], bBase + ks * 4096 + bOff[ni]);
#pragma unroll
            for (int mi = 0; mi < 4; mi++)
#pragma unroll
                for (int ni = 0; ni < 4; ni++)
                    mma_f16(acc[mi][ni], a[mi], b[ni]);
        }
        __syncthreads();
    }

#pragma unroll
    for (int mi = 0; mi < 4; mi++) {
        long r0 = mbase + wm + mi * 16 + gid;
        long r1 = r0 + 8;
        float n0 = 0.f, n1 = 0.f;
        if (EPI == 1) {
            n0 = (r0 < NV) ? d_norm[r0] : 0.f;
            n1 = (r1 < NV) ? d_norm[r1] : 0.f;
        }
#pragma unroll
        for (int ni = 0; ni < 4; ni++) {
            int col = nbase + wn + ni * 8 + 2 * qid;
            float b0 = bias[col], b1v = bias[col + 1];
            float v00 = fmaxf(acc[mi][ni][0] + b0, 0.f);
            float v01 = fmaxf(acc[mi][ni][1] + b1v, 0.f);
            float v10 = fmaxf(acc[mi][ni][2] + b0, 0.f);
            float v11 = fmaxf(acc[mi][ni][3] + b1v, 0.f);
            if (EPI == 0) {
                *(float2*)&C[r0 * 256 + col] = make_float2(v00, v01);
                *(float2*)&C[r1 * 256 + col] = make_float2(v10, v11);
            } else {
                *(__half2*)&xOut[r0 * 256 + col] = __floats2half2_rn(v00, v01);
                *(__half2*)&xOut[r1 * 256 + col] = __floats2half2_rn(v10, v11);
                if (r0 < NV)
                    *(__half2*)&sOut[r0 * 256 + col] = __floats2half2_rn(v00 * n0, v01 * n0);
                if (r1 < NV)
                    *(__half2*)&sOut[r1 * 256 + col] = __floats2half2_rn(v10 * n1, v11 * n1);
            }
        }
    }
}

// segment max over sorted graph_ids; pooled pre-zeroed (relu outputs >= 0)
__global__ void k_segmax(const float* __restrict__ x, const int* __restrict__ gid,
                         int rowsPerBlock) {
    int col = threadIdx.x;
    int r0 = blockIdx.x * rowsPerBlock;
    if (r0 >= NV) return;
    int r1 = min(r0 + rowsPerBlock, NV);
    int g = __ldg(&gid[r0]);
    float m = 0.f;
    for (int r = r0; r < r1; r++) {
        int g2 = __ldg(&gid[r]);
        if (g2 != g) {
            atomicMax((int*)&d_pooled[g * HIDN + col], __float_as_int(m));
            m = 0.f;
            g = g2;
        }
        m = fmaxf(m, x[(long)r * HIDN + col]);
    }
    atomicMax((int*)&d_pooled[g * HIDN + col], __float_as_int(m));
}

__global__ void k_head(const float* __restrict__ Wc, const float* __restrict__ bc,
                       float* __restrict__ out) {
    int t = blockIdx.x * blockDim.x + threadIdx.x;
    if (t >= NG * 10) return;
    int g = t / 10, c = t % 10;
    float s = bc[c];
#pragma unroll 8
    for (int h = 0; h < HIDN; h++) s = fmaf(d_pooled[g * HIDN + h], Wc[h * 10 + c], s);
    out[t] = s;
}

// ---------------- launch ----------------
extern "C" void kernel_launch(void* const* d_in, const int* in_sizes, int n_in,
                              void* d_out, int out_size) {
    const float* h   = (const float*)d_in[0];
    const int*   src = (const int*)d_in[1];
    const int*   dst = (const int*)d_in[2];
    const int*   gid = (const int*)d_in[3];
    const float* W1  = (const float*)d_in[4];
    const float* b1  = (const float*)d_in[5];
    const float* W2  = (const float*)d_in[6];
    const float* b2  = (const float*)d_in[7];
    const float* Wc  = (const float*)d_in[8];
    const float* bc  = (const float*)d_in[9];
    float* out = (float*)d_out;
    const int E = in_sizes[1];

    float *x2_, *pl_;
    __half *h16_, *hop1_, *hop2_, *x1h_, *g1_, *g2_, *sA_, *sB_, *w1h_, *w2h_;
    int *cnt_;
    cudaGetSymbolAddress((void**)&h16_,  d_h16);
    cudaGetSymbolAddress((void**)&hop1_, d_hop1);
    cudaGetSymbolAddress((void**)&hop2_, d_hop2);
    cudaGetSymbolAddress((void**)&x1h_,  d_x1h);
    cudaGetSymbolAddress((void**)&g1_,   d_g1);
    cudaGetSymbolAddress((void**)&g2_,   d_g2);
    cudaGetSymbolAddress((void**)&sA_,   d_sA);
    cudaGetSymbolAddress((void**)&sB_,   d_sB);
    cudaGetSymbolAddress((void**)&x2_,   d_x2);
    cudaGetSymbolAddress((void**)&pl_,   d_pooled);
    cudaGetSymbolAddress((void**)&w1h_,  d_w1h);
    cudaGetSymbolAddress((void**)&w2h_,  d_w2h);
    cudaGetSymbolAddress((void**)&cnt_,  d_cnt);

    cudaFuncSetAttribute((const void*)k_gemm_f16<1, 7>,
                         cudaFuncAttributeMaxDynamicSharedMemorySize, GEMM_SMEM_BYTES);
    cudaFuncSetAttribute((const void*)k_gemm_f16<0, 8>,
                         cudaFuncAttributeMaxDynamicSharedMemorySize, GEMM_SMEM_BYTES);

    // ---- degree, norm, CSR ----
    k_zero<<<(NV / 4 + 255) / 256, 256>>>((float4*)cnt_, NV / 4);
    k_degi<<<(E + 255) / 256, 256>>>(dst, E);
    k_norm_from_cnt<<<(NV + 255) / 256, 256>>>();
    const int NB = (NV + 1023) / 1024;
    k_scan_local<<<NB, 256>>>();
    k_scan_blk<<<1, 32>>>(NB);
    k_addoff<<<(NV + 255) / 256, 256>>>(E);
    k_csrbuild<<<(E + 255) / 256, 256>>>(src, dst, E);

    // ---- weights -> fp16 ----
    k_roundh<<<(384 * 128 + 255) / 256, 256>>>(w1h_, W1, 384 * 128);
    k_roundh<<<(768 * 128 + 255) / 256, 256>>>(w2h_, W2, 768 * 128);

    // ---- layer 1 (d=128) ----
    k_prep0<<<(unsigned)(((long)NV * 16 + 255) / 256), 256>>>((const float4*)h,
                                                              (uint4*)h16_, (uint4*)sA_);
    k_agg<128, true ><<<(NV + 15) / 16, 256>>>(sA_, hop1_, sB_);
    k_agg<128, false><<<(NV + 15) / 16, 256>>>(sB_, hop2_, nullptr);
    k_gemm_f16<1, 7><<<dim3(2, MPAD / 128), 256, GEMM_SMEM_BYTES>>>(
        h16_, hop1_, hop2_, w1h_, b1, nullptr, 384, x1h_, sA_);

    // ---- layer 2 (d=256) ----
    k_agg<256, true ><<<(NV + 7) / 8, 256>>>(sA_, g1_, sB_);
    k_agg<256, false><<<(NV + 7) / 8, 256>>>(sB_, g2_, nullptr);
    k_gemm_f16<0, 8><<<dim3(2, MPAD / 128), 256, GEMM_SMEM_BYTES>>>(
        x1h_, g1_, g2_, w2h_, b2, x2_, 768, nullptr, nullptr);

    // ---- pooling + head ----
    k_zero<<<(NG * HIDN / 4 + 255) / 256, 256>>>((float4*)pl_, NG * HIDN / 4);
    k_segmax<<<(NV + 511) / 512, 256>>>(x2_, gid, 512);
    k_head<<<3, 256>>>(Wc, bc, out);
}

// round 6
// speedup vs baseline: 5.9033x; 1.0257x over previous
#include <cuda_runtime.h>
#include <cuda_fp16.h>
#include <cstdint>

#define NV   100000
#define MPAD 100096          // 782 * 128
#define NG   64
#define HIDN 256
#define EMAX 3211264

// ---------------- scratch (device globals; no allocation allowed) ----------------
__device__ float  d_norm[NV];
__device__ int    d_cnt[NV];
__device__ int    d_rowptr[NV + 1];
__device__ int    d_cursor[NV];
__device__ int    d_blktot[128];
__device__ int    d_blkoff[128];
__device__ int    d_esrc[EMAX];
__device__ __half d_h16 [(size_t)MPAD * 128];   // GEMM1 slot0 (pad rows stay 0)
__device__ __half d_hop1[(size_t)MPAD * 128];   // GEMM1 slot1
__device__ __half d_hop2[(size_t)MPAD * 128];   // GEMM1 slot2
__device__ __half d_x1h [(size_t)MPAD * 256];   // GEMM2 slot0
__device__ __half d_g1  [(size_t)MPAD * 256];   // GEMM2 slot1
__device__ __half d_g2  [(size_t)MPAD * 256];   // GEMM2 slot2
__device__ __half d_sA  [(size_t)NV * 256];     // gather source ping
__device__ __half d_sB  [(size_t)NV * 256];     // gather source pong
__device__ __half d_w1h[384 * 256];
__device__ __half d_w2h[768 * 256];
__device__ float  d_pooled[NG * HIDN];

// ---------------- utility kernels ----------------
__global__ void k_zero(float4* __restrict__ p, long n4) {
    long i = (long)blockIdx.x * blockDim.x + threadIdx.x;
    if (i < n4) p[i] = make_float4(0.f, 0.f, 0.f, 0.f);
}

__global__ void k_degi(const int* __restrict__ dst, int E) {
    int i = blockIdx.x * blockDim.x + threadIdx.x;
    if (i < E) atomicAdd(&d_cnt[dst[i]], 1);
}

__global__ void k_norm_from_cnt() {
    int i = blockIdx.x * blockDim.x + threadIdx.x;
    if (i < NV) d_norm[i] = rsqrtf(fmaxf((float)d_cnt[i], 1.0f));
}

// ---------------- prefix scan (1024 elems / block) ----------------
__global__ __launch_bounds__(256) void k_scan_local() {
    __shared__ int sh[256];
    int b = blockIdx.x, t = threadIdx.x;
    int base = b * 1024 + t * 4;
    int c[4];
#pragma unroll
    for (int i = 0; i < 4; i++) c[i] = (base + i < NV) ? d_cnt[base + i] : 0;
    int sum = c[0] + c[1] + c[2] + c[3];
    sh[t] = sum;
    __syncthreads();
    for (int off = 1; off < 256; off <<= 1) {
        int x = (t >= off) ? sh[t - off] : 0;
        __syncthreads();
        sh[t] += x;
        __syncthreads();
    }
    int run = sh[t] - sum;
#pragma unroll
    for (int i = 0; i < 4; i++) {
        if (base + i < NV) d_rowptr[base + i] = run;
        run += c[i];
    }
    if (t == 255) d_blktot[b] = sh[255];
}

__global__ void k_scan_blk(int nb) {
    if (threadIdx.x == 0) {
        int run = 0;
        for (int b = 0; b < nb; b++) { d_blkoff[b] = run; run += d_blktot[b]; }
    }
}

__global__ void k_addoff(int E) {
    int i = blockIdx.x * blockDim.x + threadIdx.x;
    if (i < NV) {
        int v = d_rowptr[i] + d_blkoff[i >> 10];
        d_rowptr[i] = v;
        d_cursor[i] = v;
    }
    if (i == 0) d_rowptr[NV] = E;
}

__global__ void k_csrbuild(const int* __restrict__ src, const int* __restrict__ dst, int E) {
    int e = blockIdx.x * blockDim.x + threadIdx.x;
    if (e < E) {
        int p = atomicAdd(&d_cursor[dst[e]], 1);
        d_esrc[p] = src[e];
    }
}

// fp32 -> fp16 weight conversion
__global__ void k_roundh(__half* __restrict__ o, const float* __restrict__ in, int n2) {
    int i = blockIdx.x * blockDim.x + threadIdx.x;
    if (i < n2) {
        float2 v = ((const float2*)in)[i];
        ((__half2*)o)[i] = __floats2half2_rn(v.x, v.y);
    }
}

__device__ __forceinline__ uint4 pack8h(const float* f) {
    __half2 h0 = __floats2half2_rn(f[0], f[1]);
    __half2 h1 = __floats2half2_rn(f[2], f[3]);
    __half2 h2 = __floats2half2_rn(f[4], f[5]);
    __half2 h3 = __floats2half2_rn(f[6], f[7]);
    uint4 u;
    u.x = *(uint32_t*)&h0; u.y = *(uint32_t*)&h1;
    u.z = *(uint32_t*)&h2; u.w = *(uint32_t*)&h3;
    return u;
}

// prep0: h16 = fp16(h); sA = fp16(h * norm).  idx over NV*16 (8 floats each)
__global__ void k_prep0(const float4* __restrict__ in, uint4* __restrict__ h16,
                        uint4* __restrict__ s) {
    long idx = (long)blockIdx.x * blockDim.x + threadIdx.x;
    if (idx >= (long)NV * 16) return;
    int i = (int)(idx >> 4);
    float n = d_norm[i];
    float4 v0 = in[idx * 2], v1 = in[idx * 2 + 1];
    float f[8]  = {v0.x, v0.y, v0.z, v0.w, v1.x, v1.y, v1.z, v1.w};
    float fs[8];
#pragma unroll
    for (int k = 0; k < 8; k++) fs[k] = f[k] * n;
    h16[idx] = pack8h(f);
    s[idx]   = pack8h(fs);
}

// ---------------- CSR aggregation ----------------
// One group of D/8 lanes per node; each lane owns 8 halves (one uint4).
// cur = (sum s[esrc[e]]) * norm[v];  hop[v]=fp16(cur) (streaming);  s_next[v]=fp16(cur*norm[v])
template <int D, bool WRITE_S>
__global__ __launch_bounds__(256) void k_agg(const __half* __restrict__ s,
                                             __half* __restrict__ hop,
                                             __half* __restrict__ s_next) {
    const int LPE = D / 8;
    const int gpb = 256 / LPE;
    int v = blockIdx.x * gpb + threadIdx.x / LPE;
    int lane = threadIdx.x % LPE;
    if (v >= NV) return;
    int beg = __ldg(&d_rowptr[v]);
    int end = __ldg(&d_rowptr[v + 1]);
    float a0[8], a1[8], a2[8], a3[8];
#pragma unroll
    for (int i = 0; i < 8; i++) { a0[i] = 0.f; a1[i] = 0.f; a2[i] = 0.f; a3[i] = 0.f; }

    auto accum = [&](float* a, int node) {
        const uint4 u = __ldg((const uint4*)(s + (size_t)node * D) + lane);
        float2 f0 = __half22float2(*(const __half2*)&u.x);
        float2 f1 = __half22float2(*(const __half2*)&u.y);
        float2 f2 = __half22float2(*(const __half2*)&u.z);
        float2 f3 = __half22float2(*(const __half2*)&u.w);
        a[0] += f0.x; a[1] += f0.y; a[2] += f1.x; a[3] += f1.y;
        a[4] += f2.x; a[5] += f2.y; a[6] += f3.x; a[7] += f3.y;
    };

    int e = beg;
    for (; e + 3 < end; e += 4) {
        int s0 = __ldg(&d_esrc[e]);
        int s1 = __ldg(&d_esrc[e + 1]);
        int s2 = __ldg(&d_esrc[e + 2]);
        int s3 = __ldg(&d_esrc[e + 3]);
        accum(a0, s0); accum(a1, s1); accum(a2, s2); accum(a3, s3);
    }
    for (; e < end; e++) accum(a0, __ldg(&d_esrc[e]));

    float n = __ldg(&d_norm[v]);
    float cur[8], curn[8];
#pragma unroll
    for (int i = 0; i < 8; i++) {
        cur[i] = ((a0[i] + a1[i]) + (a2[i] + a3[i])) * n;
        curn[i] = cur[i] * n;
    }

    uint4 uh = pack8h(cur);
    __stcs((float4*)((uint4*)(hop + (size_t)v * D) + lane), *(float4*)&uh);
    if (WRITE_S)
        ((uint4*)(s_next + (size_t)v * D))[lane] = pack8h(curn);
}

// ---------------- fp16 tensor-core GEMM (ldmatrix + m16n8k16, 3-stage) ----------------
#define BM 128
#define BN 128
#define BKH 64                   // k-halves per tile (128 bytes)
#define A_BYTES (BM * 128)       // 16384
#define B_BYTES (BKH * 256)      // 16384
#define STAGE_BYTES (A_BYTES + B_BYTES)
#define NSTAGE 3
#define GEMM_SMEM_BYTES (NSTAGE * STAGE_BYTES)
// fused-pool epilogue smem: 128 x 132 fp32 tile + 128 gids = 67584 + 512 <= 96KB
#define POOL_STRIDE 132

extern __shared__ char smem_gemm[];

__device__ __forceinline__ void cp16(uint32_t s, const void* g) {
    asm volatile("cp.async.cg.shared.global [%0], [%1], 16;\n" :: "r"(s), "l"(g));
}
__device__ __forceinline__ void cp_commit() { asm volatile("cp.async.commit_group;\n"); }
template <int N>
__device__ __forceinline__ void cp_wait() { asm volatile("cp.async.wait_group %0;\n" :: "n"(N)); }

__device__ __forceinline__ void ldsm4(uint32_t* r, uint32_t a) {
    asm volatile("ldmatrix.sync.aligned.m8n8.x4.shared.b16 {%0,%1,%2,%3}, [%4];"
                 : "=r"(r[0]), "=r"(r[1]), "=r"(r[2]), "=r"(r[3]) : "r"(a));
}
__device__ __forceinline__ void ldsm2t(uint32_t* r, uint32_t a) {
    asm volatile("ldmatrix.sync.aligned.m8n8.x2.trans.shared.b16 {%0,%1}, [%2];"
                 : "=r"(r[0]), "=r"(r[1]) : "r"(a));
}

__device__ __forceinline__ void mma_f16(float* c, const uint32_t* a, const uint32_t* b) {
    asm volatile(
        "mma.sync.aligned.m16n8k16.row.col.f32.f16.f16.f32 "
        "{%0,%1,%2,%3}, {%4,%5,%6,%7}, {%8,%9}, {%0,%1,%2,%3};"
        : "+f"(c[0]), "+f"(c[1]), "+f"(c[2]), "+f"(c[3])
        : "r"(a[0]), "r"(a[1]), "r"(a[2]), "r"(a[3]), "r"(b[0]), "r"(b[1]));
}

// EPI=0: fused segment-max pooling into d_pooled (needs gidp; sorted graph ids)
// EPI=1: xOut(fp16)[row*256+col] = relu; sOut(fp16) = relu*norm (rows < NV)
template <int EPI, int SWS>
__global__ __launch_bounds__(256) void k_gemm_f16(const __half* __restrict__ S0,
                                                  const __half* __restrict__ S1,
                                                  const __half* __restrict__ S2,
                                                  const __half* __restrict__ Bh,
                                                  const float* __restrict__ bias,
                                                  const int* __restrict__ gidp, int Kdim,
                                                  __half* __restrict__ xOut,
                                                  __half* __restrict__ sOut) {
    const int SW = 1 << SWS;
    const int tid  = threadIdx.x;
    const int lane = tid & 31, warp = tid >> 5;
    const int gid  = lane >> 2, qid = lane & 3;
    const int wm   = (warp & 1) * 64;
    const int wn   = (warp >> 1) * 32;
    const long mbase = (long)blockIdx.y * BM;
    const int  nbase = blockIdx.x * BN;

    float acc[4][4][4];
#pragma unroll
    for (int mi = 0; mi < 4; mi++)
#pragma unroll
        for (int ni = 0; ni < 4; ni++)
#pragma unroll
            for (int r = 0; r < 4; r++) acc[mi][ni][r] = 0.f;

    const uint32_t smemB = (uint32_t)__cvta_generic_to_shared(smem_gemm);
    const int ntiles = Kdim / BKH;

    auto load_stage = [&](int t, int buf) {
        uint32_t sb = smemB + buf * STAGE_BYTES;
#pragma unroll
        for (int i = 0; i < 4; i++) {
            int ch = tid + 256 * i;
            int r = ch >> 3, kc = ch & 7;
            uint32_t dstA = sb + r * 128 + ((kc * 16) ^ ((r & 7) * 16));
            int kh = t * BKH + kc * 8;
            int sl = kh >> SWS;
            int off = kh & (SW - 1);
            const __half* base = (sl == 0) ? S0 : ((sl == 1) ? S1 : S2);
            cp16(dstA, base + (size_t)(mbase + r) * SW + off);
        }
#pragma unroll
        for (int i = 0; i < 4; i++) {
            int ch = tid + 256 * i;
            int r = ch >> 4, nc = ch & 15;
            uint32_t dstB = sb + A_BYTES + r * 256 + ((nc * 16) ^ ((r & 7) * 16));
            cp16(dstB, Bh + (size_t)(t * BKH + r) * 256 + nbase + nc * 8);
        }
        cp_commit();
    };

    const int Lr = lane & 7, sub = lane >> 3;
    const int rowLocal = Lr + (sub & 1) * 8;
    const int ksub16 = (sub >> 1) * 16;
    const uint32_t xorA = Lr * 16;
    const int bl = lane & 15;
    const uint32_t xorB = (lane & 7) * 16;

    load_stage(0, 0);
    load_stage(1, 1);
    for (int t = 0; t < ntiles; t++) {
        if (t + 2 < ntiles) { load_stage(t + 2, (t + 2) % NSTAGE); cp_wait<2>(); }
        else if (t + 1 < ntiles) cp_wait<1>();
        else cp_wait<0>();
        __syncthreads();
        uint32_t As = smemB + (t % NSTAGE) * STAGE_BYTES;
        uint32_t Bs = As + A_BYTES;
        uint32_t aRow[4];
#pragma unroll
        for (int mi = 0; mi < 4; mi++)
            aRow[mi] = As + (wm + mi * 16 + rowLocal) * 128;
        uint32_t bBase = Bs + bl * 256;
        uint32_t bOff[4];
#pragma unroll
        for (int ni = 0; ni < 4; ni++)
            bOff[ni] = (uint32_t)((wn + ni * 8) * 2) ^ xorB;
#pragma unroll
        for (int ks = 0; ks < 4; ks++) {
            uint32_t a[4][4], b[4][2];
#pragma unroll
            for (int mi = 0; mi < 4; mi++)
                ldsm4(a[mi], aRow[mi] + (uint32_t)((ks * 32 + ksub16) ^ xorA));
#pragma unroll
            for (int ni = 0; ni < 4; ni++)
                ldsm2t(b[ni], bBase + ks * 4096 + bOff[ni]);
#pragma unroll
            for (int mi = 0; mi < 4; mi++)
#pragma unroll
                for (int ni = 0; ni < 4; ni++)
                    mma_f16(acc[mi][ni], a[mi], b[ni]);
        }
        __syncthreads();
    }

    if (EPI == 1) {
#pragma unroll
        for (int mi = 0; mi < 4; mi++) {
            long r0 = mbase + wm + mi * 16 + gid;
            long r1 = r0 + 8;
            float n0 = (r0 < NV) ? d_norm[r0] : 0.f;
            float n1 = (r1 < NV) ? d_norm[r1] : 0.f;
#pragma unroll
            for (int ni = 0; ni < 4; ni++) {
                int col = nbase + wn + ni * 8 + 2 * qid;
                float b0 = bias[col], b1v = bias[col + 1];
                float v00 = fmaxf(acc[mi][ni][0] + b0, 0.f);
                float v01 = fmaxf(acc[mi][ni][1] + b1v, 0.f);
                float v10 = fmaxf(acc[mi][ni][2] + b0, 0.f);
                float v11 = fmaxf(acc[mi][ni][3] + b1v, 0.f);
                *(__half2*)&xOut[r0 * 256 + col] = __floats2half2_rn(v00, v01);
                *(__half2*)&xOut[r1 * 256 + col] = __floats2half2_rn(v10, v11);
                if (r0 < NV)
                    *(__half2*)&sOut[r0 * 256 + col] = __floats2half2_rn(v00 * n0, v01 * n0);
                if (r1 < NV)
                    *(__half2*)&sOut[r1 * 256 + col] = __floats2half2_rn(v10 * n1, v11 * n1);
            }
        }
    } else {
        // ---- fused segment-max pooling ----
        float* pool = (float*)smem_gemm;                         // [128][POOL_STRIDE]
        int* gsh = (int*)(smem_gemm + 128 * POOL_STRIDE * 4);    // [128]
#pragma unroll
        for (int mi = 0; mi < 4; mi++) {
            int rr0 = wm + mi * 16 + gid;
            int rr1 = rr0 + 8;
#pragma unroll
            for (int ni = 0; ni < 4; ni++) {
                int c = wn + ni * 8 + 2 * qid;
                float b0 = bias[nbase + c], b1v = bias[nbase + c + 1];
                pool[rr0 * POOL_STRIDE + c]     = fmaxf(acc[mi][ni][0] + b0, 0.f);
                pool[rr0 * POOL_STRIDE + c + 1] = fmaxf(acc[mi][ni][1] + b1v, 0.f);
                pool[rr1 * POOL_STRIDE + c]     = fmaxf(acc[mi][ni][2] + b0, 0.f);
                pool[rr1 * POOL_STRIDE + c + 1] = fmaxf(acc[mi][ni][3] + b1v, 0.f);
            }
        }
        if (tid < 128) {
            long r = mbase + tid;
            gsh[tid] = (r < NV) ? __ldg(&gidp[r]) : -1;
        }
        __syncthreads();
        if (tid < 128) {
            int col = tid;
            int g = gsh[0];
            float m = 0.f;
            for (int r = 0; r < 128; r++) {
                int g2 = gsh[r];
                if (g2 < 0) break;
                if (g2 != g) {
                    atomicMax((int*)&d_pooled[g * HIDN + nbase + col], __float_as_int(m));
                    m = 0.f;
                    g = g2;
                }
                m = fmaxf(m, pool[r * POOL_STRIDE + col]);
            }
            if (g >= 0)
                atomicMax((int*)&d_pooled[g * HIDN + nbase + col], __float_as_int(m));
        }
    }
}

__global__ void k_head(const float* __restrict__ Wc, const float* __restrict__ bc,
                       float* __restrict__ out) {
    int t = blockIdx.x * blockDim.x + threadIdx.x;
    if (t >= NG * 10) return;
    int g = t / 10, c = t % 10;
    float s = bc[c];
#pragma unroll 8
    for (int h = 0; h < HIDN; h++) s = fmaf(d_pooled[g * HIDN + h], Wc[h * 10 + c], s);
    out[t] = s;
}

// ---------------- launch ----------------
extern "C" void kernel_launch(void* const* d_in, const int* in_sizes, int n_in,
                              void* d_out, int out_size) {
    const float* h   = (const float*)d_in[0];
    const int*   src = (const int*)d_in[1];
    const int*   dst = (const int*)d_in[2];
    const int*   gid = (const int*)d_in[3];
    const float* W1  = (const float*)d_in[4];
    const float* b1  = (const float*)d_in[5];
    const float* W2  = (const float*)d_in[6];
    const float* b2  = (const float*)d_in[7];
    const float* Wc  = (const float*)d_in[8];
    const float* bc  = (const float*)d_in[9];
    float* out = (float*)d_out;
    const int E = in_sizes[1];

    float *pl_;
    __half *h16_, *hop1_, *hop2_, *x1h_, *g1_, *g2_, *sA_, *sB_, *w1h_, *w2h_;
    int *cnt_;
    cudaGetSymbolAddress((void**)&h16_,  d_h16);
    cudaGetSymbolAddress((void**)&hop1_, d_hop1);
    cudaGetSymbolAddress((void**)&hop2_, d_hop2);
    cudaGetSymbolAddress((void**)&x1h_,  d_x1h);
    cudaGetSymbolAddress((void**)&g1_,   d_g1);
    cudaGetSymbolAddress((void**)&g2_,   d_g2);
    cudaGetSymbolAddress((void**)&sA_,   d_sA);
    cudaGetSymbolAddress((void**)&sB_,   d_sB);
    cudaGetSymbolAddress((void**)&pl_,   d_pooled);
    cudaGetSymbolAddress((void**)&w1h_,  d_w1h);
    cudaGetSymbolAddress((void**)&w2h_,  d_w2h);
    cudaGetSymbolAddress((void**)&cnt_,  d_cnt);

    cudaFuncSetAttribute((const void*)k_gemm_f16<1, 7>,
                         cudaFuncAttributeMaxDynamicSharedMemorySize, GEMM_SMEM_BYTES);
    cudaFuncSetAttribute((const void*)k_gemm_f16<0, 8>,
                         cudaFuncAttributeMaxDynamicSharedMemorySize, GEMM_SMEM_BYTES);

    // ---- degree, norm, CSR ----
    k_zero<<<(NV / 4 + 255) / 256, 256>>>((float4*)cnt_, NV / 4);
    k_degi<<<(E + 255) / 256, 256>>>(dst, E);
    k_norm_from_cnt<<<(NV + 255) / 256, 256>>>();
    const int NB = (NV + 1023) / 1024;
    k_scan_local<<<NB, 256>>>();
    k_scan_blk<<<1, 32>>>(NB);
    k_addoff<<<(NV + 255) / 256, 256>>>(E);
    k_csrbuild<<<(E + 255) / 256, 256>>>(src, dst, E);

    // ---- weights -> fp16 ----
    k_roundh<<<(384 * 128 + 255) / 256, 256>>>(w1h_, W1, 384 * 128);
    k_roundh<<<(768 * 128 + 255) / 256, 256>>>(w2h_, W2, 768 * 128);

    // ---- layer 1 (d=128) ----
    k_prep0<<<(unsigned)(((long)NV * 16 + 255) / 256), 256>>>((const float4*)h,
                                                              (uint4*)h16_, (uint4*)sA_);
    k_agg<128, true ><<<(NV + 15) / 16, 256>>>(sA_, hop1_, sB_);
    k_agg<128, false><<<(NV + 15) / 16, 256>>>(sB_, hop2_, nullptr);
    k_gemm_f16<1, 7><<<dim3(2, MPAD / 128), 256, GEMM_SMEM_BYTES>>>(
        h16_, hop1_, hop2_, w1h_, b1, nullptr, 384, x1h_, sA_);

    // ---- layer 2 (d=256) ----
    k_agg<256, true ><<<(NV + 7) / 8, 256>>>(sA_, g1_, sB_);
    k_agg<256, false><<<(NV + 7) / 8, 256>>>(sB_, g2_, nullptr);
    k_zero<<<(NG * HIDN / 4 + 255) / 256, 256>>>((float4*)pl_, NG * HIDN / 4);
    k_gemm_f16<0, 8><<<dim3(2, MPAD / 128), 256, GEMM_SMEM_BYTES>>>(
        x1h_, g1_, g2_, w2h_, b2, gid, 768, nullptr, nullptr);

    // ---- head ----
    k_head<<<3, 256>>>(Wc, bc, out);
}